// round 1
// baseline (speedup 1.0000x reference)
#include <cuda_runtime.h>
#include <math.h>

#define E_DIM 1024
#define S_LEN 2048
#define B_SZ  2
#define H_NUM 16
#define DKH   64
#define M_TOT (B_SZ * S_LEN)     // 4096
#define N_QKV (3 * E_DIM)        // 3072

// Scratch (allocation-free: __device__ globals). 64 MB total.
__device__ float g_q[(size_t)B_SZ * H_NUM * S_LEN * DKH];
__device__ float g_k[(size_t)B_SZ * H_NUM * S_LEN * DKH];
__device__ float g_v[(size_t)B_SZ * H_NUM * S_LEN * DKH];
__device__ float g_ctx[(size_t)B_SZ * S_LEN * E_DIM];

// ---------------------------------------------------------------------------
// SGEMM: C[M,N] = A[M,K] @ W[N,K]^T + bias[N]
// 128x128 tile, BK=8, 256 threads, 8x8 micro-tile per thread.
// MODE 0: A = x, W = w_in; epilogue scatters q/k/v into head-major scratch.
// MODE 1: A = g_ctx, W = w_out; epilogue writes row-major output.
// ---------------------------------------------------------------------------
template <int MODE>
__global__ __launch_bounds__(256) void sgemm_kernel(
    const float* __restrict__ A, const float* __restrict__ W,
    const float* __restrict__ bias, float* __restrict__ Cout, int K)
{
    __shared__ float As[8][128];
    __shared__ float Bs[8][128];

    const int tid = threadIdx.x;
    const int tx  = tid & 15;     // 0..15  -> col fragment
    const int ty  = tid >> 4;     // 0..15  -> row fragment
    const int m0  = blockIdx.y * 128;
    const int n0  = blockIdx.x * 128;

    const int lr = tid >> 1;            // 0..127 row within tile (loads)
    const int lc = (tid & 1) * 4;       // 0 or 4

    const float* Aptr = (MODE == 0 ? A : g_ctx);
    Aptr += (size_t)(m0 + lr) * K + lc;
    const float* Wptr = W + (size_t)(n0 + lr) * K + lc;

    float acc[8][8];
#pragma unroll
    for (int i = 0; i < 8; i++)
#pragma unroll
        for (int j = 0; j < 8; j++) acc[i][j] = 0.f;

    for (int k0 = 0; k0 < K; k0 += 8) {
        float4 av = *(const float4*)(Aptr + k0);
        float4 wv = *(const float4*)(Wptr + k0);
        __syncthreads();
        As[lc + 0][lr] = av.x; As[lc + 1][lr] = av.y;
        As[lc + 2][lr] = av.z; As[lc + 3][lr] = av.w;
        Bs[lc + 0][lr] = wv.x; Bs[lc + 1][lr] = wv.y;
        Bs[lc + 2][lr] = wv.z; Bs[lc + 3][lr] = wv.w;
        __syncthreads();
#pragma unroll
        for (int kk = 0; kk < 8; kk++) {
            float a[8], b[8];
            *(float4*)&a[0] = *(const float4*)&As[kk][ty * 8];
            *(float4*)&a[4] = *(const float4*)&As[kk][ty * 8 + 4];
            *(float4*)&b[0] = *(const float4*)&Bs[kk][tx * 8];
            *(float4*)&b[4] = *(const float4*)&Bs[kk][tx * 8 + 4];
#pragma unroll
            for (int i = 0; i < 8; i++)
#pragma unroll
                for (int j = 0; j < 8; j++)
                    acc[i][j] = fmaf(a[i], b[j], acc[i][j]);
        }
    }

#pragma unroll
    for (int i = 0; i < 8; i++) {
        const int m    = m0 + ty * 8 + i;
        const int bb   = m >> 11;       // batch
        const int srow = m & (S_LEN - 1);
#pragma unroll
        for (int j = 0; j < 8; j++) {
            const int n = n0 + tx * 8 + j;
            const float v = acc[i][j] + bias[n];
            if (MODE == 0) {
                const int part = n >> 10;        // 0=q 1=k 2=v
                const int e    = n & 1023;
                const int h    = e >> 6;
                const int d    = e & 63;
                float* dst = (part == 0) ? g_q : (part == 1) ? g_k : g_v;
                dst[((((size_t)bb * H_NUM + h) * S_LEN) + srow) * DKH + d] = v;
            } else {
                Cout[(size_t)m * E_DIM + n] = v;
            }
        }
    }
}

// ---------------------------------------------------------------------------
// Flash attention (fp32, causal). One block per (q-tile 64, head, batch).
// 256 threads as (tx=16, ty=16); each thread owns a 4x4 fragment.
// Smem: Qt (d-major, stride 64), KV (Kt d-major / V row-major, stride 64),
//       Pt (j-major, stride 65 — reads are broadcast so pad only helps writes).
// ---------------------------------------------------------------------------
__global__ __launch_bounds__(256) void attn_kernel()
{
    extern __shared__ __align__(16) float sm[];
    float* Qt = sm;                  // Qt[d*64 + i]
    float* KV = sm + 64 * 64;        // K phase: Kt[d*64 + j]; V phase: V[j*64 + d]
    float* Pt = sm + 2 * 64 * 64;    // Pt[j*65 + i]

    const int tid = threadIdx.x;
    const int tx  = tid & 15;
    const int ty  = tid >> 4;
    const int qi  = blockIdx.x;
    const int h   = blockIdx.y;
    const int b   = blockIdx.z;

    const size_t base = (((size_t)b * H_NUM + h) * S_LEN) * DKH;
    const float* Qg = g_q + base;
    const float* Kg = g_k + base;
    const float* Vg = g_v + base;
    const int q0 = qi * 64;

    // Load Q transposed: lanes vary over row -> conflict-free transposed stores.
#pragma unroll
    for (int u = 0; u < 4; u++) {
        const int fidx = tid + u * 256;
        const int row  = fidx & 63;
        const int c4   = (fidx >> 6) * 4;
        const float4 v = *(const float4*)&Qg[(size_t)(q0 + row) * DKH + c4];
        Qt[(c4 + 0) * 64 + row] = v.x;
        Qt[(c4 + 1) * 64 + row] = v.y;
        Qt[(c4 + 2) * 64 + row] = v.z;
        Qt[(c4 + 3) * 64 + row] = v.w;
    }

    float o[4][4];
    float m_i[4], l_i[4];
#pragma unroll
    for (int i = 0; i < 4; i++) {
        m_i[i] = -1e30f; l_i[i] = 0.f;
#pragma unroll
        for (int j = 0; j < 4; j++) o[i][j] = 0.f;
    }

    const int i0 = ty * 4;       // rows owned
    const int j0 = tx * 4;       // cols owned (S phase) / d cols owned (O phase)
    const float scale = 0.125f;  // 1/sqrt(64)

    for (int t = 0; t <= qi; t++) {
        __syncthreads();   // previous-iteration KV/Pt reads complete
        // Load K tile transposed.
#pragma unroll
        for (int u = 0; u < 4; u++) {
            const int fidx = tid + u * 256;
            const int row  = fidx & 63;
            const int c4   = (fidx >> 6) * 4;
            const float4 v = *(const float4*)&Kg[(size_t)(t * 64 + row) * DKH + c4];
            KV[(c4 + 0) * 64 + row] = v.x;
            KV[(c4 + 1) * 64 + row] = v.y;
            KV[(c4 + 2) * 64 + row] = v.z;
            KV[(c4 + 3) * 64 + row] = v.w;
        }
        __syncthreads();

        // S = Q K^T (4x4 fragment), contiguous LDS.128 frags.
        float s[4][4];
#pragma unroll
        for (int i = 0; i < 4; i++)
#pragma unroll
            for (int j = 0; j < 4; j++) s[i][j] = 0.f;
#pragma unroll 8
        for (int d = 0; d < 64; d++) {
            const float4 qf = *(const float4*)&Qt[d * 64 + i0];
            const float4 kf = *(const float4*)&KV[d * 64 + j0];
            const float qa[4] = {qf.x, qf.y, qf.z, qf.w};
            const float ka[4] = {kf.x, kf.y, kf.z, kf.w};
#pragma unroll
            for (int i = 0; i < 4; i++)
#pragma unroll
                for (int j = 0; j < 4; j++)
                    s[i][j] = fmaf(qa[i], ka[j], s[i][j]);
        }

        // Scale, then causal mask on the diagonal tile.
#pragma unroll
        for (int i = 0; i < 4; i++)
#pragma unroll
            for (int j = 0; j < 4; j++) {
                s[i][j] *= scale;
                if (t == qi && (j0 + j) > (i0 + i)) s[i][j] = -1e30f;
            }

        // Row max across the 16 tx-lanes (width-16 xor shuffles).
        float rmax[4];
#pragma unroll
        for (int i = 0; i < 4; i++) {
            float v = fmaxf(fmaxf(s[i][0], s[i][1]), fmaxf(s[i][2], s[i][3]));
#pragma unroll
            for (int off = 8; off >= 1; off >>= 1)
                v = fmaxf(v, __shfl_xor_sync(0xffffffffu, v, off, 16));
            rmax[i] = v;
        }

        float mnew[4], alpha[4], rsum[4];
#pragma unroll
        for (int i = 0; i < 4; i++) {
            mnew[i]  = fmaxf(m_i[i], rmax[i]);
            alpha[i] = __expf(m_i[i] - mnew[i]);
            rsum[i]  = 0.f;
        }
#pragma unroll
        for (int i = 0; i < 4; i++)
#pragma unroll
            for (int j = 0; j < 4; j++) {
                const float p = __expf(s[i][j] - mnew[i]);
                s[i][j] = p;
                rsum[i] += p;
            }
#pragma unroll
        for (int i = 0; i < 4; i++) {
            float v = rsum[i];
#pragma unroll
            for (int off = 8; off >= 1; off >>= 1)
                v += __shfl_xor_sync(0xffffffffu, v, off, 16);
            l_i[i] = l_i[i] * alpha[i] + v;
            m_i[i] = mnew[i];
#pragma unroll
            for (int j = 0; j < 4; j++) o[i][j] *= alpha[i];
        }

        // Stash P transposed (stride 65 -> only 2-way write conflicts).
#pragma unroll
        for (int i = 0; i < 4; i++)
#pragma unroll
            for (int j = 0; j < 4; j++)
                Pt[(j0 + j) * 65 + (i0 + i)] = s[i][j];
        __syncthreads();   // P visible; everyone done reading K

        // Load V tile row-major (coalesced, conflict-free float4 stores).
#pragma unroll
        for (int u = 0; u < 4; u++) {
            const int fidx = tid + u * 256;
            const int row  = fidx >> 4;
            const int c4   = (fidx & 15) * 4;
            const float4 v = *(const float4*)&Vg[(size_t)(t * 64 + row) * DKH + c4];
            *(float4*)&KV[row * 64 + c4] = v;
        }
        __syncthreads();

        // O += P V : P reads broadcast, V frags contiguous LDS.128.
#pragma unroll 8
        for (int j = 0; j < 64; j++) {
            const float p0 = Pt[j * 65 + i0];
            const float p1 = Pt[j * 65 + i0 + 1];
            const float p2 = Pt[j * 65 + i0 + 2];
            const float p3 = Pt[j * 65 + i0 + 3];
            const float4 vf = *(const float4*)&KV[j * 64 + j0];
            o[0][0] = fmaf(p0, vf.x, o[0][0]); o[0][1] = fmaf(p0, vf.y, o[0][1]);
            o[0][2] = fmaf(p0, vf.z, o[0][2]); o[0][3] = fmaf(p0, vf.w, o[0][3]);
            o[1][0] = fmaf(p1, vf.x, o[1][0]); o[1][1] = fmaf(p1, vf.y, o[1][1]);
            o[1][2] = fmaf(p1, vf.z, o[1][2]); o[1][3] = fmaf(p1, vf.w, o[1][3]);
            o[2][0] = fmaf(p2, vf.x, o[2][0]); o[2][1] = fmaf(p2, vf.y, o[2][1]);
            o[2][2] = fmaf(p2, vf.z, o[2][2]); o[2][3] = fmaf(p2, vf.w, o[2][3]);
            o[3][0] = fmaf(p3, vf.x, o[3][0]); o[3][1] = fmaf(p3, vf.y, o[3][1]);
            o[3][2] = fmaf(p3, vf.z, o[3][2]); o[3][3] = fmaf(p3, vf.w, o[3][3]);
        }
    }

    // Epilogue: normalize and write context in (B,S,E) layout (concat heads).
#pragma unroll
    for (int i = 0; i < 4; i++) {
        const float inv = 1.0f / l_i[i];
        float4 v;
        v.x = o[i][0] * inv; v.y = o[i][1] * inv;
        v.z = o[i][2] * inv; v.w = o[i][3] * inv;
        float* dst = &g_ctx[((size_t)b * S_LEN + (q0 + i0 + i)) * E_DIM + h * DKH + j0];
        *(float4*)dst = v;
    }
}

// ---------------------------------------------------------------------------
extern "C" void kernel_launch(void* const* d_in, const int* in_sizes, int n_in,
                              void* d_out, int out_size)
{
    (void)in_sizes; (void)n_in; (void)out_size;
    const float* x     = (const float*)d_in[0];
    const float* w_in  = (const float*)d_in[1];
    const float* b_in  = (const float*)d_in[2];
    const float* w_out = (const float*)d_in[3];
    const float* b_out = (const float*)d_in[4];
    float* out = (float*)d_out;

    // 1) QKV projection -> head-major q/k/v scratch
    {
        dim3 grid(N_QKV / 128, M_TOT / 128);
        sgemm_kernel<0><<<grid, 256>>>(x, w_in, b_in, nullptr, E_DIM);
    }
    // 2) Causal flash attention -> g_ctx (B,S,E)
    {
        const int smem = (2 * 64 * 64 + 64 * 65) * (int)sizeof(float);  // 49408 B
        cudaFuncSetAttribute(attn_kernel,
                             cudaFuncAttributeMaxDynamicSharedMemorySize, smem);
        dim3 grid(S_LEN / 64, H_NUM, B_SZ);
        attn_kernel<<<grid, 256, smem>>>();
    }
    // 3) Output projection -> d_out
    {
        dim3 grid(E_DIM / 128, M_TOT / 128);
        sgemm_kernel<1><<<grid, 256>>>(nullptr, w_out, b_out, out, E_DIM);
    }
}

// round 3
// speedup vs baseline: 1.6871x; 1.6871x over previous
#include <cuda_runtime.h>
#include <cstdint>
#include <math.h>

#define E_DIM 1024
#define S_LEN 2048
#define B_SZ  2
#define H_NUM 16
#define DKH   64
#define M_TOT (B_SZ * S_LEN)     // 4096
#define N_QKV (3 * E_DIM)        // 3072

// Scratch (allocation-free: __device__ globals).
__device__ float g_q[(size_t)B_SZ * H_NUM * S_LEN * DKH];
__device__ float g_k[(size_t)B_SZ * H_NUM * S_LEN * DKH];
__device__ float g_v[(size_t)B_SZ * H_NUM * S_LEN * DKH];
__device__ float g_ctx[(size_t)B_SZ * S_LEN * E_DIM];

__device__ __forceinline__ uint32_t f2tf32(float x) {
    uint32_t r;
    asm("cvt.rna.tf32.f32 %0, %1;" : "=r"(r) : "f"(x));
    return r;
}

__device__ __forceinline__ void mma_tf32(float& c0, float& c1, float& c2, float& c3,
                                         uint32_t a0, uint32_t a1, uint32_t a2, uint32_t a3,
                                         uint32_t b0, uint32_t b1) {
    asm volatile(
        "mma.sync.aligned.m16n8k8.row.col.f32.tf32.tf32.f32 "
        "{%0,%1,%2,%3}, {%4,%5,%6,%7}, {%8,%9}, {%0,%1,%2,%3};"
        : "+f"(c0), "+f"(c1), "+f"(c2), "+f"(c3)
        : "r"(a0), "r"(a1), "r"(a2), "r"(a3), "r"(b0), "r"(b1));
}

// ---------------------------------------------------------------------------
// TF32 mma.sync GEMM: C[M,N] = A[M,1024] @ W[N,1024]^T + bias[N]
// 128x128 tile, BK=32, 256 threads (8 warps, 2x4), warp tile 64x32.
// Smem stride 36 floats: fragment LDS bank = (4g+tig) mod 32 -> conflict-free.
// MODE 0: A=x, scatter epilogue into g_q/g_k/g_v.  MODE 1: A=g_ctx, row-major C.
// ---------------------------------------------------------------------------
#define BK 32
#define NKT (E_DIM / BK)   // 32
#define STR 36             // smem row stride (floats)

template <int MODE>
__global__ __launch_bounds__(256, 2) void gemm_mma(
    const float* __restrict__ Ain, const float* __restrict__ W,
    const float* __restrict__ bias, float* __restrict__ Cout)
{
    extern __shared__ __align__(16) uint32_t sm[];
    uint32_t* As = sm;                 // [128][STR]
    uint32_t* Bs = sm + 128 * STR;     // [128][STR]

    const int tid  = threadIdx.x;
    const int warp = tid >> 5;
    const int lane = tid & 31;
    const int g    = lane >> 2;        // 0..7
    const int tg   = lane & 3;         // 0..3
    const int wm   = warp >> 2;        // 0..1 -> m offset 64*wm
    const int wn   = warp & 3;         // 0..3 -> n offset 32*wn

    const int m0 = blockIdx.y * 128;
    const int n0 = blockIdx.x * 128;

    const float* A = (MODE == 0 ? Ain : (const float*)g_ctx);

    // global load geometry: each thread 4 float4 per operand per k-tile
    const int lrow  = tid >> 1;             // 0..127
    const int cbase = (tid & 1) * 16;       // 0 or 16
    const float* pA = A + (size_t)(m0 + lrow) * E_DIM + cbase;
    const float* pW = W + (size_t)(n0 + lrow) * E_DIM + cbase;

    float acc[4][4][4];
#pragma unroll
    for (int mt = 0; mt < 4; mt++)
#pragma unroll
        for (int nt = 0; nt < 4; nt++)
#pragma unroll
            for (int r = 0; r < 4; r++) acc[mt][nt][r] = 0.f;

    float4 ra[4], rw[4];
#pragma unroll
    for (int u = 0; u < 4; u++) {
        ra[u] = *(const float4*)(pA + 4 * u);
        rw[u] = *(const float4*)(pW + 4 * u);
    }

    for (int kt = 0; kt < NKT; kt++) {
        // store current regs (converted to tf32)
#pragma unroll
        for (int u = 0; u < 4; u++) {
            uint32_t* da = &As[lrow * STR + cbase + 4 * u];
            da[0] = f2tf32(ra[u].x); da[1] = f2tf32(ra[u].y);
            da[2] = f2tf32(ra[u].z); da[3] = f2tf32(ra[u].w);
            uint32_t* db = &Bs[lrow * STR + cbase + 4 * u];
            db[0] = f2tf32(rw[u].x); db[1] = f2tf32(rw[u].y);
            db[2] = f2tf32(rw[u].z); db[3] = f2tf32(rw[u].w);
        }
        __syncthreads();

        // prefetch next k-tile
        if (kt + 1 < NKT) {
            const int k0 = (kt + 1) * BK;
#pragma unroll
            for (int u = 0; u < 4; u++) {
                ra[u] = *(const float4*)(pA + k0 + 4 * u);
                rw[u] = *(const float4*)(pW + k0 + 4 * u);
            }
        }

        // compute: 4 k-steps of m16n8k8
#pragma unroll
        for (int ks = 0; ks < 4; ks++) {
            const int kb = ks * 8;
            uint32_t a[4][4];
#pragma unroll
            for (int mt = 0; mt < 4; mt++) {
                const int m = wm * 64 + mt * 16 + g;
                a[mt][0] = As[m * STR + kb + tg];
                a[mt][1] = As[(m + 8) * STR + kb + tg];
                a[mt][2] = As[m * STR + kb + tg + 4];
                a[mt][3] = As[(m + 8) * STR + kb + tg + 4];
            }
            uint32_t b[4][2];
#pragma unroll
            for (int nt = 0; nt < 4; nt++) {
                const int n = wn * 32 + nt * 8 + g;
                b[nt][0] = Bs[n * STR + kb + tg];
                b[nt][1] = Bs[n * STR + kb + tg + 4];
            }
#pragma unroll
            for (int mt = 0; mt < 4; mt++)
#pragma unroll
                for (int nt = 0; nt < 4; nt++)
                    mma_tf32(acc[mt][nt][0], acc[mt][nt][1],
                             acc[mt][nt][2], acc[mt][nt][3],
                             a[mt][0], a[mt][1], a[mt][2], a[mt][3],
                             b[nt][0], b[nt][1]);
        }
        __syncthreads();
    }

    // Epilogue: per-thread fragments, bias add, direct store (float2).
#pragma unroll
    for (int mt = 0; mt < 4; mt++) {
#pragma unroll
        for (int nt = 0; nt < 4; nt++) {
            const int col = n0 + wn * 32 + nt * 8 + 2 * tg;
            const float b0 = bias[col];
            const float b1 = bias[col + 1];
#pragma unroll
            for (int half = 0; half < 2; half++) {
                const int m = m0 + wm * 64 + mt * 16 + g + half * 8;
                float2 v;
                v.x = acc[mt][nt][half * 2 + 0] + b0;
                v.y = acc[mt][nt][half * 2 + 1] + b1;
                if (MODE == 0) {
                    const int bb   = m >> 11;
                    const int srow = m & (S_LEN - 1);
                    const int part = col >> 10;
                    const int e    = col & 1023;
                    const int h    = e >> 6;
                    const int d    = e & 63;
                    float* dst = (part == 0) ? g_q : (part == 1) ? g_k : g_v;
                    *(float2*)&dst[((((size_t)bb * H_NUM + h) * S_LEN) + srow) * DKH + d] = v;
                } else {
                    *(float2*)&Cout[(size_t)m * E_DIM + col] = v;
                }
            }
        }
    }
}

// ---------------------------------------------------------------------------
// Flash attention (fp32, causal) — unchanged from R0 (passing version).
// ---------------------------------------------------------------------------
__global__ __launch_bounds__(256) void attn_kernel()
{
    extern __shared__ __align__(16) float smf[];
    float* Qt = smf;
    float* KV = smf + 64 * 64;
    float* Pt = smf + 2 * 64 * 64;

    const int tid = threadIdx.x;
    const int tx  = tid & 15;
    const int ty  = tid >> 4;
    const int qi  = blockIdx.x;
    const int h   = blockIdx.y;
    const int b   = blockIdx.z;

    const size_t base = (((size_t)b * H_NUM + h) * S_LEN) * DKH;
    const float* Qg = g_q + base;
    const float* Kg = g_k + base;
    const float* Vg = g_v + base;
    const int q0 = qi * 64;

#pragma unroll
    for (int u = 0; u < 4; u++) {
        const int fidx = tid + u * 256;
        const int row  = fidx & 63;
        const int c4   = (fidx >> 6) * 4;
        const float4 v = *(const float4*)&Qg[(size_t)(q0 + row) * DKH + c4];
        Qt[(c4 + 0) * 64 + row] = v.x;
        Qt[(c4 + 1) * 64 + row] = v.y;
        Qt[(c4 + 2) * 64 + row] = v.z;
        Qt[(c4 + 3) * 64 + row] = v.w;
    }

    float o[4][4];
    float m_i[4], l_i[4];
#pragma unroll
    for (int i = 0; i < 4; i++) {
        m_i[i] = -1e30f; l_i[i] = 0.f;
#pragma unroll
        for (int j = 0; j < 4; j++) o[i][j] = 0.f;
    }

    const int i0 = ty * 4;
    const int j0 = tx * 4;
    const float scale = 0.125f;

    for (int t = 0; t <= qi; t++) {
        __syncthreads();
#pragma unroll
        for (int u = 0; u < 4; u++) {
            const int fidx = tid + u * 256;
            const int row  = fidx & 63;
            const int c4   = (fidx >> 6) * 4;
            const float4 v = *(const float4*)&Kg[(size_t)(t * 64 + row) * DKH + c4];
            KV[(c4 + 0) * 64 + row] = v.x;
            KV[(c4 + 1) * 64 + row] = v.y;
            KV[(c4 + 2) * 64 + row] = v.z;
            KV[(c4 + 3) * 64 + row] = v.w;
        }
        __syncthreads();

        float s[4][4];
#pragma unroll
        for (int i = 0; i < 4; i++)
#pragma unroll
            for (int j = 0; j < 4; j++) s[i][j] = 0.f;
#pragma unroll 8
        for (int d = 0; d < 64; d++) {
            const float4 qf = *(const float4*)&Qt[d * 64 + i0];
            const float4 kf = *(const float4*)&KV[d * 64 + j0];
            const float qa[4] = {qf.x, qf.y, qf.z, qf.w};
            const float ka[4] = {kf.x, kf.y, kf.z, kf.w};
#pragma unroll
            for (int i = 0; i < 4; i++)
#pragma unroll
                for (int j = 0; j < 4; j++)
                    s[i][j] = fmaf(qa[i], ka[j], s[i][j]);
        }

#pragma unroll
        for (int i = 0; i < 4; i++)
#pragma unroll
            for (int j = 0; j < 4; j++) {
                s[i][j] *= scale;
                if (t == qi && (j0 + j) > (i0 + i)) s[i][j] = -1e30f;
            }

        float rmax[4];
#pragma unroll
        for (int i = 0; i < 4; i++) {
            float v = fmaxf(fmaxf(s[i][0], s[i][1]), fmaxf(s[i][2], s[i][3]));
#pragma unroll
            for (int off = 8; off >= 1; off >>= 1)
                v = fmaxf(v, __shfl_xor_sync(0xffffffffu, v, off, 16));
            rmax[i] = v;
        }

        float mnew[4], alpha[4], rsum[4];
#pragma unroll
        for (int i = 0; i < 4; i++) {
            mnew[i]  = fmaxf(m_i[i], rmax[i]);
            alpha[i] = __expf(m_i[i] - mnew[i]);
            rsum[i]  = 0.f;
        }
#pragma unroll
        for (int i = 0; i < 4; i++)
#pragma unroll
            for (int j = 0; j < 4; j++) {
                const float p = __expf(s[i][j] - mnew[i]);
                s[i][j] = p;
                rsum[i] += p;
            }
#pragma unroll
        for (int i = 0; i < 4; i++) {
            float v = rsum[i];
#pragma unroll
            for (int off = 8; off >= 1; off >>= 1)
                v += __shfl_xor_sync(0xffffffffu, v, off, 16);
            l_i[i] = l_i[i] * alpha[i] + v;
            m_i[i] = mnew[i];
#pragma unroll
            for (int j = 0; j < 4; j++) o[i][j] *= alpha[i];
        }

#pragma unroll
        for (int i = 0; i < 4; i++)
#pragma unroll
            for (int j = 0; j < 4; j++)
                Pt[(j0 + j) * 65 + (i0 + i)] = s[i][j];
        __syncthreads();

#pragma unroll
        for (int u = 0; u < 4; u++) {
            const int fidx = tid + u * 256;
            const int row  = fidx >> 4;
            const int c4   = (fidx & 15) * 4;
            const float4 v = *(const float4*)&Vg[(size_t)(t * 64 + row) * DKH + c4];
            *(float4*)&KV[row * 64 + c4] = v;
        }
        __syncthreads();

#pragma unroll 8
        for (int j = 0; j < 64; j++) {
            const float p0 = Pt[j * 65 + i0];
            const float p1 = Pt[j * 65 + i0 + 1];
            const float p2 = Pt[j * 65 + i0 + 2];
            const float p3 = Pt[j * 65 + i0 + 3];
            const float4 vf = *(const float4*)&KV[j * 64 + j0];
            o[0][0] = fmaf(p0, vf.x, o[0][0]); o[0][1] = fmaf(p0, vf.y, o[0][1]);
            o[0][2] = fmaf(p0, vf.z, o[0][2]); o[0][3] = fmaf(p0, vf.w, o[0][3]);
            o[1][0] = fmaf(p1, vf.x, o[1][0]); o[1][1] = fmaf(p1, vf.y, o[1][1]);
            o[1][2] = fmaf(p1, vf.z, o[1][2]); o[1][3] = fmaf(p1, vf.w, o[1][3]);
            o[2][0] = fmaf(p2, vf.x, o[2][0]); o[2][1] = fmaf(p2, vf.y, o[2][1]);
            o[2][2] = fmaf(p2, vf.z, o[2][2]); o[2][3] = fmaf(p2, vf.w, o[2][3]);
            o[3][0] = fmaf(p3, vf.x, o[3][0]); o[3][1] = fmaf(p3, vf.y, o[3][1]);
            o[3][2] = fmaf(p3, vf.z, o[3][2]); o[3][3] = fmaf(p3, vf.w, o[3][3]);
        }
    }

#pragma unroll
    for (int i = 0; i < 4; i++) {
        const float inv = 1.0f / l_i[i];
        float4 v;
        v.x = o[i][0] * inv; v.y = o[i][1] * inv;
        v.z = o[i][2] * inv; v.w = o[i][3] * inv;
        float* dst = &g_ctx[((size_t)b * S_LEN + (q0 + i0 + i)) * E_DIM + h * DKH + j0];
        *(float4*)dst = v;
    }
}

// ---------------------------------------------------------------------------
extern "C" void kernel_launch(void* const* d_in, const int* in_sizes, int n_in,
                              void* d_out, int out_size)
{
    (void)in_sizes; (void)n_in; (void)out_size;
    const float* x     = (const float*)d_in[0];
    const float* w_in  = (const float*)d_in[1];
    const float* b_in  = (const float*)d_in[2];
    const float* w_out = (const float*)d_in[3];
    const float* b_out = (const float*)d_in[4];
    float* out = (float*)d_out;

    const int gemm_smem = 2 * 128 * STR * (int)sizeof(uint32_t);   // 36864 B
    const int attn_smem = (2 * 64 * 64 + 64 * 65) * (int)sizeof(float);

    static bool attr_done = false;
    if (!attr_done) {
        cudaFuncSetAttribute(gemm_mma<0>, cudaFuncAttributeMaxDynamicSharedMemorySize, gemm_smem);
        cudaFuncSetAttribute(gemm_mma<1>, cudaFuncAttributeMaxDynamicSharedMemorySize, gemm_smem);
        cudaFuncSetAttribute(attn_kernel, cudaFuncAttributeMaxDynamicSharedMemorySize, attn_smem);
        attr_done = true;
    }

    // 1) QKV projection (tf32 mma.sync) -> head-major q/k/v scratch
    {
        dim3 grid(N_QKV / 128, M_TOT / 128);
        gemm_mma<0><<<grid, 256, gemm_smem>>>(x, w_in, b_in, nullptr);
    }
    // 2) Causal flash attention -> g_ctx (B,S,E)
    {
        dim3 grid(S_LEN / 64, H_NUM, B_SZ);
        attn_kernel<<<grid, 256, attn_smem>>>();
    }
    // 3) Output projection (tf32 mma.sync) -> d_out
    {
        dim3 grid(E_DIM / 128, M_TOT / 128);
        gemm_mma<1><<<grid, 256, gemm_smem>>>(nullptr, w_out, b_out, out);
    }
}

// round 4
// speedup vs baseline: 2.4838x; 1.4723x over previous
#include <cuda_runtime.h>
#include <cstdint>
#include <math.h>

#define E_DIM 1024
#define S_LEN 2048
#define B_SZ  2
#define H_NUM 16
#define DKH   64
#define M_TOT (B_SZ * S_LEN)     // 4096
#define N_QKV (3 * E_DIM)        // 3072

// Scratch (allocation-free: __device__ globals).
__device__ float g_q[(size_t)B_SZ * H_NUM * S_LEN * DKH];
__device__ float g_k[(size_t)B_SZ * H_NUM * S_LEN * DKH];
__device__ float g_v[(size_t)B_SZ * H_NUM * S_LEN * DKH];
__device__ float g_ctx[(size_t)B_SZ * S_LEN * E_DIM];

__device__ __forceinline__ uint32_t f2tf32(float x) {
    uint32_t r;
    asm("cvt.rna.tf32.f32 %0, %1;" : "=r"(r) : "f"(x));
    return r;
}

__device__ __forceinline__ void mma_tf32(float& c0, float& c1, float& c2, float& c3,
                                         uint32_t a0, uint32_t a1, uint32_t a2, uint32_t a3,
                                         uint32_t b0, uint32_t b1) {
    asm volatile(
        "mma.sync.aligned.m16n8k8.row.col.f32.tf32.tf32.f32 "
        "{%0,%1,%2,%3}, {%4,%5,%6,%7}, {%8,%9}, {%0,%1,%2,%3};"
        : "+f"(c0), "+f"(c1), "+f"(c2), "+f"(c3)
        : "r"(a0), "r"(a1), "r"(a2), "r"(a3), "r"(b0), "r"(b1));
}

// fast 2^y for y <= 0 (clamped at -126). All fma/alu pipe, no MUFU.
__device__ __forceinline__ float exp2p(float y) {
    y = fmaxf(y, -126.0f);
    float n = floorf(y);
    float f = y - n;
    float p = 1.53456767e-4f;
    p = fmaf(p, f, 1.33335581e-3f);
    p = fmaf(p, f, 9.61812910e-3f);
    p = fmaf(p, f, 5.55041087e-2f);
    p = fmaf(p, f, 2.40226507e-1f);
    p = fmaf(p, f, 6.93147181e-1f);
    p = fmaf(p, f, 1.0f);
    const int e = (int)n + 127;
    return p * __int_as_float(e << 23);
}

// ---------------------------------------------------------------------------
// TF32 mma.sync GEMM (unchanged from R2): C = A @ W^T + bias
// ---------------------------------------------------------------------------
#define BK 32
#define NKT (E_DIM / BK)
#define STR 36

template <int MODE>
__global__ __launch_bounds__(256, 2) void gemm_mma(
    const float* __restrict__ Ain, const float* __restrict__ W,
    const float* __restrict__ bias, float* __restrict__ Cout)
{
    extern __shared__ __align__(16) uint32_t sm[];
    uint32_t* As = sm;
    uint32_t* Bs = sm + 128 * STR;

    const int tid  = threadIdx.x;
    const int warp = tid >> 5;
    const int lane = tid & 31;
    const int g    = lane >> 2;
    const int tg   = lane & 3;
    const int wm   = warp >> 2;
    const int wn   = warp & 3;

    const int m0 = blockIdx.y * 128;
    const int n0 = blockIdx.x * 128;

    const float* A = (MODE == 0 ? Ain : (const float*)g_ctx);

    const int lrow  = tid >> 1;
    const int cbase = (tid & 1) * 16;
    const float* pA = A + (size_t)(m0 + lrow) * E_DIM + cbase;
    const float* pW = W + (size_t)(n0 + lrow) * E_DIM + cbase;

    float acc[4][4][4];
#pragma unroll
    for (int mt = 0; mt < 4; mt++)
#pragma unroll
        for (int nt = 0; nt < 4; nt++)
#pragma unroll
            for (int r = 0; r < 4; r++) acc[mt][nt][r] = 0.f;

    float4 ra[4], rw[4];
#pragma unroll
    for (int u = 0; u < 4; u++) {
        ra[u] = *(const float4*)(pA + 4 * u);
        rw[u] = *(const float4*)(pW + 4 * u);
    }

    for (int kt = 0; kt < NKT; kt++) {
#pragma unroll
        for (int u = 0; u < 4; u++) {
            uint32_t* da = &As[lrow * STR + cbase + 4 * u];
            da[0] = f2tf32(ra[u].x); da[1] = f2tf32(ra[u].y);
            da[2] = f2tf32(ra[u].z); da[3] = f2tf32(ra[u].w);
            uint32_t* db = &Bs[lrow * STR + cbase + 4 * u];
            db[0] = f2tf32(rw[u].x); db[1] = f2tf32(rw[u].y);
            db[2] = f2tf32(rw[u].z); db[3] = f2tf32(rw[u].w);
        }
        __syncthreads();

        if (kt + 1 < NKT) {
            const int k0 = (kt + 1) * BK;
#pragma unroll
            for (int u = 0; u < 4; u++) {
                ra[u] = *(const float4*)(pA + k0 + 4 * u);
                rw[u] = *(const float4*)(pW + k0 + 4 * u);
            }
        }

#pragma unroll
        for (int ks = 0; ks < 4; ks++) {
            const int kb = ks * 8;
            uint32_t a[4][4];
#pragma unroll
            for (int mt = 0; mt < 4; mt++) {
                const int m = wm * 64 + mt * 16 + g;
                a[mt][0] = As[m * STR + kb + tg];
                a[mt][1] = As[(m + 8) * STR + kb + tg];
                a[mt][2] = As[m * STR + kb + tg + 4];
                a[mt][3] = As[(m + 8) * STR + kb + tg + 4];
            }
            uint32_t b[4][2];
#pragma unroll
            for (int nt = 0; nt < 4; nt++) {
                const int n = wn * 32 + nt * 8 + g;
                b[nt][0] = Bs[n * STR + kb + tg];
                b[nt][1] = Bs[n * STR + kb + tg + 4];
            }
#pragma unroll
            for (int mt = 0; mt < 4; mt++)
#pragma unroll
                for (int nt = 0; nt < 4; nt++)
                    mma_tf32(acc[mt][nt][0], acc[mt][nt][1],
                             acc[mt][nt][2], acc[mt][nt][3],
                             a[mt][0], a[mt][1], a[mt][2], a[mt][3],
                             b[nt][0], b[nt][1]);
        }
        __syncthreads();
    }

#pragma unroll
    for (int mt = 0; mt < 4; mt++) {
#pragma unroll
        for (int nt = 0; nt < 4; nt++) {
            const int col = n0 + wn * 32 + nt * 8 + 2 * tg;
            const float b0 = bias[col];
            const float b1 = bias[col + 1];
#pragma unroll
            for (int half = 0; half < 2; half++) {
                const int m = m0 + wm * 64 + mt * 16 + g + half * 8;
                float2 v;
                v.x = acc[mt][nt][half * 2 + 0] + b0;
                v.y = acc[mt][nt][half * 2 + 1] + b1;
                if (MODE == 0) {
                    const int bb   = m >> 11;
                    const int srow = m & (S_LEN - 1);
                    const int part = col >> 10;
                    const int e    = col & 1023;
                    const int h    = e >> 6;
                    const int d    = e & 63;
                    float* dst = (part == 0) ? g_q : (part == 1) ? g_k : g_v;
                    *(float2*)&dst[((((size_t)bb * H_NUM + h) * S_LEN) + srow) * DKH + d] = v;
                } else {
                    *(float2*)&Cout[(size_t)m * E_DIM + col] = v;
                }
            }
        }
    }
}

// ---------------------------------------------------------------------------
// Tensor-core flash attention (tf32 mma.sync, causal, poly-exp softmax).
// Block = 64 q-rows, 128 threads (4 warps); warp owns 16 q-rows.
// kv-tile = 64. Smem: Ks[64][68] (tf32 bits; staged Q first), Vt[64][68].
// ---------------------------------------------------------------------------
#define ASTR 68   // 68 mod 32 == 4 -> fragment bank = 4g+tg, conflict-free

__global__ __launch_bounds__(128, 4) void attn_mma()
{
    extern __shared__ __align__(16) uint32_t asm_[];
    uint32_t* Ks = asm_;               // [64][ASTR]
    uint32_t* Vt = asm_ + 64 * ASTR;   // [64][ASTR] (d-major)

    const int tid  = threadIdx.x;
    const int warp = tid >> 5;
    const int lane = tid & 31;
    const int g    = lane >> 2;
    const int tg   = lane & 3;

    const int qi = blockIdx.x;
    const int h  = blockIdx.y;
    const int b  = blockIdx.z;
    const int q0 = qi * 64;

    const size_t base = (((size_t)b * H_NUM + h) * S_LEN) * DKH;
    const float* Qg = g_q + base;
    const float* Kg = g_k + base;
    const float* Vg = g_v + base;

    // --- stage Q into Ks region, extract per-warp A fragments ---
    const int lrow = tid >> 1;
    const int cb   = (tid & 1) * 32;
#pragma unroll
    for (int u = 0; u < 8; u++) {
        const float4 v = *(const float4*)&Qg[(size_t)(q0 + lrow) * DKH + cb + 4 * u];
        uint32_t* d = &Ks[lrow * ASTR + cb + 4 * u];
        d[0] = f2tf32(v.x); d[1] = f2tf32(v.y); d[2] = f2tf32(v.z); d[3] = f2tf32(v.w);
    }
    __syncthreads();

    uint32_t qf[8][4];
    const int mrow = 16 * warp + g;
#pragma unroll
    for (int ks = 0; ks < 8; ks++) {
        qf[ks][0] = Ks[mrow * ASTR + 8 * ks + tg];
        qf[ks][1] = Ks[(mrow + 8) * ASTR + 8 * ks + tg];
        qf[ks][2] = Ks[mrow * ASTR + 8 * ks + tg + 4];
        qf[ks][3] = Ks[(mrow + 8) * ASTR + 8 * ks + tg + 4];
    }

    float o[8][4];
#pragma unroll
    for (int nt = 0; nt < 8; nt++)
#pragma unroll
        for (int r = 0; r < 4; r++) o[nt][r] = 0.f;
    float m2a = -1e30f, m2b = -1e30f, la = 0.f, lb = 0.f;

    const float SC = 0.125f * 1.44269504088896341f;  // scale * log2(e)

    for (int t = 0; t <= qi; t++) {
        __syncthreads();   // done with previous Ks/Vt (or Q frags on iter 0)
        // load K tile -> Ks (tf32), V tile -> Vt transposed (tf32)
#pragma unroll
        for (int u = 0; u < 8; u++) {
            const float4 kv = *(const float4*)&Kg[(size_t)(t * 64 + lrow) * DKH + cb + 4 * u];
            uint32_t* d = &Ks[lrow * ASTR + cb + 4 * u];
            d[0] = f2tf32(kv.x); d[1] = f2tf32(kv.y); d[2] = f2tf32(kv.z); d[3] = f2tf32(kv.w);
            const float4 vv = *(const float4*)&Vg[(size_t)(t * 64 + lrow) * DKH + cb + 4 * u];
            Vt[(cb + 4 * u + 0) * ASTR + lrow] = f2tf32(vv.x);
            Vt[(cb + 4 * u + 1) * ASTR + lrow] = f2tf32(vv.y);
            Vt[(cb + 4 * u + 2) * ASTR + lrow] = f2tf32(vv.z);
            Vt[(cb + 4 * u + 3) * ASTR + lrow] = f2tf32(vv.w);
        }
        __syncthreads();

        // S = Q K^T
        float sacc[8][4];
#pragma unroll
        for (int nt = 0; nt < 8; nt++) {
            sacc[nt][0] = 0.f; sacc[nt][1] = 0.f; sacc[nt][2] = 0.f; sacc[nt][3] = 0.f;
            const int n = 8 * nt + g;
#pragma unroll
            for (int ks = 0; ks < 8; ks++) {
                const uint32_t b0 = Ks[n * ASTR + 8 * ks + tg];
                const uint32_t b1 = Ks[n * ASTR + 8 * ks + tg + 4];
                mma_tf32(sacc[nt][0], sacc[nt][1], sacc[nt][2], sacc[nt][3],
                         qf[ks][0], qf[ks][1], qf[ks][2], qf[ks][3], b0, b1);
            }
        }

        // scale (base-2 domain) + causal mask on diagonal tile
#pragma unroll
        for (int nt = 0; nt < 8; nt++) {
#pragma unroll
            for (int r = 0; r < 4; r++) sacc[nt][r] *= SC;
            if (t == qi) {
                const int c0 = 8 * nt + 2 * tg;
                const int ra = 16 * warp + g, rb = ra + 8;
                if (c0 > ra)     sacc[nt][0] = -1e30f;
                if (c0 + 1 > ra) sacc[nt][1] = -1e30f;
                if (c0 > rb)     sacc[nt][2] = -1e30f;
                if (c0 + 1 > rb) sacc[nt][3] = -1e30f;
            }
        }

        // row max (rows g and g+8) -> quad reduce
        float rmaxa = -1e30f, rmaxb = -1e30f;
#pragma unroll
        for (int nt = 0; nt < 8; nt++) {
            rmaxa = fmaxf(rmaxa, fmaxf(sacc[nt][0], sacc[nt][1]));
            rmaxb = fmaxf(rmaxb, fmaxf(sacc[nt][2], sacc[nt][3]));
        }
        rmaxa = fmaxf(rmaxa, __shfl_xor_sync(0xffffffffu, rmaxa, 1));
        rmaxa = fmaxf(rmaxa, __shfl_xor_sync(0xffffffffu, rmaxa, 2));
        rmaxb = fmaxf(rmaxb, __shfl_xor_sync(0xffffffffu, rmaxb, 1));
        rmaxb = fmaxf(rmaxb, __shfl_xor_sync(0xffffffffu, rmaxb, 2));

        const float mna = fmaxf(m2a, rmaxa);
        const float mnb = fmaxf(m2b, rmaxb);
        const float alpa = exp2p(m2a - mna);
        const float alpb = exp2p(m2b - mnb);
        m2a = mna; m2b = mnb;

        // p = 2^(s - m), row sums, convert to tf32 in place
        float rsa = 0.f, rsb = 0.f;
#pragma unroll
        for (int nt = 0; nt < 8; nt++) {
            float p0 = exp2p(sacc[nt][0] - mna);
            float p1 = exp2p(sacc[nt][1] - mna);
            float p2 = exp2p(sacc[nt][2] - mnb);
            float p3 = exp2p(sacc[nt][3] - mnb);
            rsa += p0 + p1; rsb += p2 + p3;
            sacc[nt][0] = __uint_as_float(f2tf32(p0));
            sacc[nt][1] = __uint_as_float(f2tf32(p1));
            sacc[nt][2] = __uint_as_float(f2tf32(p2));
            sacc[nt][3] = __uint_as_float(f2tf32(p3));
        }
        rsa += __shfl_xor_sync(0xffffffffu, rsa, 1);
        rsa += __shfl_xor_sync(0xffffffffu, rsa, 2);
        rsb += __shfl_xor_sync(0xffffffffu, rsb, 1);
        rsb += __shfl_xor_sync(0xffffffffu, rsb, 2);
        la = la * alpa + rsa;
        lb = lb * alpb + rsb;

        // rescale O
#pragma unroll
        for (int nt = 0; nt < 8; nt++) {
            o[nt][0] *= alpa; o[nt][1] *= alpa;
            o[nt][2] *= alpb; o[nt][3] *= alpb;
        }

        // O += P V  (A-frags gathered from sacc via intra-quad shfl)
        const int src0 = (lane & ~3) | (tg >> 1);
        const int src1 = src0 + 2;
#pragma unroll
        for (int ks = 0; ks < 8; ks++) {
            const float x0 = __shfl_sync(0xffffffffu, sacc[ks][0], src0);
            const float x1 = __shfl_sync(0xffffffffu, sacc[ks][1], src0);
            const float x2 = __shfl_sync(0xffffffffu, sacc[ks][2], src0);
            const float x3 = __shfl_sync(0xffffffffu, sacc[ks][3], src0);
            const float y0 = __shfl_sync(0xffffffffu, sacc[ks][0], src1);
            const float y1 = __shfl_sync(0xffffffffu, sacc[ks][1], src1);
            const float y2 = __shfl_sync(0xffffffffu, sacc[ks][2], src1);
            const float y3 = __shfl_sync(0xffffffffu, sacc[ks][3], src1);
            const uint32_t a0 = __float_as_uint((tg & 1) ? x1 : x0);
            const uint32_t a1 = __float_as_uint((tg & 1) ? x3 : x2);
            const uint32_t a2 = __float_as_uint((tg & 1) ? y1 : y0);
            const uint32_t a3 = __float_as_uint((tg & 1) ? y3 : y2);
#pragma unroll
            for (int nt = 0; nt < 8; nt++) {
                const int n = 8 * nt + g;
                const uint32_t b0 = Vt[n * ASTR + 8 * ks + tg];
                const uint32_t b1 = Vt[n * ASTR + 8 * ks + tg + 4];
                mma_tf32(o[nt][0], o[nt][1], o[nt][2], o[nt][3],
                         a0, a1, a2, a3, b0, b1);
            }
        }
    }

    // epilogue: normalize, write g_ctx (B,S,E)
    const float inva = 1.0f / la;
    const float invb = 1.0f / lb;
    const int rowa = q0 + 16 * warp + g;
    const int rowb = rowa + 8;
#pragma unroll
    for (int nt = 0; nt < 8; nt++) {
        const int col = h * DKH + 8 * nt + 2 * tg;
        float2 va, vb;
        va.x = o[nt][0] * inva; va.y = o[nt][1] * inva;
        vb.x = o[nt][2] * invb; vb.y = o[nt][3] * invb;
        *(float2*)&g_ctx[((size_t)b * S_LEN + rowa) * E_DIM + col] = va;
        *(float2*)&g_ctx[((size_t)b * S_LEN + rowb) * E_DIM + col] = vb;
    }
}

// ---------------------------------------------------------------------------
extern "C" void kernel_launch(void* const* d_in, const int* in_sizes, int n_in,
                              void* d_out, int out_size)
{
    (void)in_sizes; (void)n_in; (void)out_size;
    const float* x     = (const float*)d_in[0];
    const float* w_in  = (const float*)d_in[1];
    const float* b_in  = (const float*)d_in[2];
    const float* w_out = (const float*)d_in[3];
    const float* b_out = (const float*)d_in[4];
    float* out = (float*)d_out;

    const int gemm_smem = 2 * 128 * STR * (int)sizeof(uint32_t);
    const int attn_smem = 2 * 64 * ASTR * (int)sizeof(uint32_t);   // 34816 B

    static bool attr_done = false;
    if (!attr_done) {
        cudaFuncSetAttribute(gemm_mma<0>, cudaFuncAttributeMaxDynamicSharedMemorySize, gemm_smem);
        cudaFuncSetAttribute(gemm_mma<1>, cudaFuncAttributeMaxDynamicSharedMemorySize, gemm_smem);
        cudaFuncSetAttribute(attn_mma, cudaFuncAttributeMaxDynamicSharedMemorySize, attn_smem);
        attr_done = true;
    }

    {
        dim3 grid(N_QKV / 128, M_TOT / 128);
        gemm_mma<0><<<grid, 256, gemm_smem>>>(x, w_in, b_in, nullptr);
    }
    {
        dim3 grid(S_LEN / 64, H_NUM, B_SZ);
        attn_mma<<<grid, 128, attn_smem>>>();
    }
    {
        dim3 grid(E_DIM / 128, M_TOT / 128);
        gemm_mma<1><<<grid, 256, gemm_smem>>>(nullptr, w_out, b_out, out);
    }
}

// round 5
// speedup vs baseline: 3.2770x; 1.3193x over previous
#include <cuda_runtime.h>
#include <cstdint>
#include <math.h>

#define E_DIM 1024
#define S_LEN 2048
#define B_SZ  2
#define H_NUM 16
#define DKH   64
#define M_TOT (B_SZ * S_LEN)     // 4096
#define N_QKV (3 * E_DIM)        // 3072

// Scratch (allocation-free: __device__ globals). q/k/v hold tf32-rounded bits.
__device__ float g_q[(size_t)B_SZ * H_NUM * S_LEN * DKH];
__device__ float g_k[(size_t)B_SZ * H_NUM * S_LEN * DKH];
__device__ float g_v[(size_t)B_SZ * H_NUM * S_LEN * DKH];
__device__ float g_ctx[(size_t)B_SZ * S_LEN * E_DIM];

__device__ __forceinline__ uint32_t f2tf32(float x) {
    uint32_t r;
    asm("cvt.rna.tf32.f32 %0, %1;" : "=r"(r) : "f"(x));
    return r;
}

__device__ __forceinline__ uint32_t smem_u32(const void* p) {
    uint32_t a;
    asm("{ .reg .u64 t; cvta.to.shared.u64 t, %1; cvt.u32.u64 %0, t; }"
        : "=r"(a) : "l"(p));
    return a;
}

__device__ __forceinline__ void cp16(uint32_t dst, const void* src) {
    asm volatile("cp.async.cg.shared.global [%0], [%1], 16;"
                 :: "r"(dst), "l"(src) : "memory");
}
#define CP_COMMIT() asm volatile("cp.async.commit_group;" ::: "memory")
#define CP_WAIT0()  asm volatile("cp.async.wait_group 0;" ::: "memory")
#define CP_WAIT1()  asm volatile("cp.async.wait_group 1;" ::: "memory")

__device__ __forceinline__ void mma_tf32(float& c0, float& c1, float& c2, float& c3,
                                         uint32_t a0, uint32_t a1, uint32_t a2, uint32_t a3,
                                         uint32_t b0, uint32_t b1) {
    asm volatile(
        "mma.sync.aligned.m16n8k8.row.col.f32.tf32.tf32.f32 "
        "{%0,%1,%2,%3}, {%4,%5,%6,%7}, {%8,%9}, {%0,%1,%2,%3};"
        : "+f"(c0), "+f"(c1), "+f"(c2), "+f"(c3)
        : "r"(a0), "r"(a1), "r"(a2), "r"(a3), "r"(b0), "r"(b1));
}

// fast 2^y for y <= 0 (clamped). fma/alu pipe only, no MUFU.
__device__ __forceinline__ float exp2p(float y) {
    y = fmaxf(y, -126.0f);
    float n = floorf(y);
    float f = y - n;
    float p = 1.53456767e-4f;
    p = fmaf(p, f, 1.33335581e-3f);
    p = fmaf(p, f, 9.61812910e-3f);
    p = fmaf(p, f, 5.55041087e-2f);
    p = fmaf(p, f, 2.40226507e-1f);
    p = fmaf(p, f, 6.93147181e-1f);
    p = fmaf(p, f, 1.0f);
    const int e = (int)n + 127;
    return p * __int_as_float(e << 23);
}

// ---------------------------------------------------------------------------
// TF32 mma.sync GEMM: C = A @ W^T + bias (STS.128 stores; MODE0 rounds output)
// ---------------------------------------------------------------------------
#define BK 32
#define NKT (E_DIM / BK)
#define STR 36

template <int MODE>
__global__ __launch_bounds__(256, 2) void gemm_mma(
    const float* __restrict__ Ain, const float* __restrict__ W,
    const float* __restrict__ bias, float* __restrict__ Cout)
{
    extern __shared__ __align__(16) uint32_t sm[];
    uint32_t* As = sm;
    uint32_t* Bs = sm + 128 * STR;

    const int tid  = threadIdx.x;
    const int warp = tid >> 5;
    const int lane = tid & 31;
    const int g    = lane >> 2;
    const int tg   = lane & 3;
    const int wm   = warp >> 2;
    const int wn   = warp & 3;

    const int m0 = blockIdx.y * 128;
    const int n0 = blockIdx.x * 128;

    const float* A = (MODE == 0 ? Ain : (const float*)g_ctx);

    const int lrow  = tid >> 1;
    const int cbase = (tid & 1) * 16;
    const float* pA = A + (size_t)(m0 + lrow) * E_DIM + cbase;
    const float* pW = W + (size_t)(n0 + lrow) * E_DIM + cbase;

    float acc[4][4][4];
#pragma unroll
    for (int mt = 0; mt < 4; mt++)
#pragma unroll
        for (int nt = 0; nt < 4; nt++)
#pragma unroll
            for (int r = 0; r < 4; r++) acc[mt][nt][r] = 0.f;

    float4 ra[4], rw[4];
#pragma unroll
    for (int u = 0; u < 4; u++) {
        ra[u] = *(const float4*)(pA + 4 * u);
        rw[u] = *(const float4*)(pW + 4 * u);
    }

    for (int kt = 0; kt < NKT; kt++) {
#pragma unroll
        for (int u = 0; u < 4; u++) {
            uint4 va, vb;
            va.x = f2tf32(ra[u].x); va.y = f2tf32(ra[u].y);
            va.z = f2tf32(ra[u].z); va.w = f2tf32(ra[u].w);
            vb.x = f2tf32(rw[u].x); vb.y = f2tf32(rw[u].y);
            vb.z = f2tf32(rw[u].z); vb.w = f2tf32(rw[u].w);
            *(uint4*)&As[lrow * STR + cbase + 4 * u] = va;
            *(uint4*)&Bs[lrow * STR + cbase + 4 * u] = vb;
        }
        __syncthreads();

        if (kt + 1 < NKT) {
            const int k0 = (kt + 1) * BK;
#pragma unroll
            for (int u = 0; u < 4; u++) {
                ra[u] = *(const float4*)(pA + k0 + 4 * u);
                rw[u] = *(const float4*)(pW + k0 + 4 * u);
            }
        }

#pragma unroll
        for (int ks = 0; ks < 4; ks++) {
            const int kb = ks * 8;
            uint32_t a[4][4];
#pragma unroll
            for (int mt = 0; mt < 4; mt++) {
                const int m = wm * 64 + mt * 16 + g;
                a[mt][0] = As[m * STR + kb + tg];
                a[mt][1] = As[(m + 8) * STR + kb + tg];
                a[mt][2] = As[m * STR + kb + tg + 4];
                a[mt][3] = As[(m + 8) * STR + kb + tg + 4];
            }
            uint32_t b[4][2];
#pragma unroll
            for (int nt = 0; nt < 4; nt++) {
                const int n = wn * 32 + nt * 8 + g;
                b[nt][0] = Bs[n * STR + kb + tg];
                b[nt][1] = Bs[n * STR + kb + tg + 4];
            }
#pragma unroll
            for (int mt = 0; mt < 4; mt++)
#pragma unroll
                for (int nt = 0; nt < 4; nt++)
                    mma_tf32(acc[mt][nt][0], acc[mt][nt][1],
                             acc[mt][nt][2], acc[mt][nt][3],
                             a[mt][0], a[mt][1], a[mt][2], a[mt][3],
                             b[nt][0], b[nt][1]);
        }
        __syncthreads();
    }

#pragma unroll
    for (int mt = 0; mt < 4; mt++) {
#pragma unroll
        for (int nt = 0; nt < 4; nt++) {
            const int col = n0 + wn * 32 + nt * 8 + 2 * tg;
            const float b0 = bias[col];
            const float b1 = bias[col + 1];
#pragma unroll
            for (int half = 0; half < 2; half++) {
                const int m = m0 + wm * 64 + mt * 16 + g + half * 8;
                float2 v;
                v.x = acc[mt][nt][half * 2 + 0] + b0;
                v.y = acc[mt][nt][half * 2 + 1] + b1;
                if (MODE == 0) {
                    // store tf32-rounded bits so attention can skip all cvt
                    v.x = __uint_as_float(f2tf32(v.x));
                    v.y = __uint_as_float(f2tf32(v.y));
                    const int bb   = m >> 11;
                    const int srow = m & (S_LEN - 1);
                    const int part = col >> 10;
                    const int e    = col & 1023;
                    const int h    = e >> 6;
                    const int d    = e & 63;
                    float* dst = (part == 0) ? g_q : (part == 1) ? g_k : g_v;
                    *(float2*)&dst[((((size_t)bb * H_NUM + h) * S_LEN) + srow) * DKH + d] = v;
                } else {
                    *(float2*)&Cout[(size_t)m * E_DIM + col] = v;
                }
            }
        }
    }
}

// ---------------------------------------------------------------------------
// Tensor-core flash attention, cp.async double-buffered (no cvt needed:
// q/k/v already tf32-rounded). 64 q-rows/CTA, 128 threads (4 warps).
// K smem stride 68 (row-major [n][k]); V smem stride 72 (row-major [j][d]).
// Both fragment LDS patterns are 32-bank conflict-free.
// ---------------------------------------------------------------------------
#define KSTR 68
#define VSTR 72
#define KBUF(b) ((b) * 64 * KSTR)                 // uint32 index
#define VBUF(b) (2 * 64 * KSTR + (b) * 64 * VSTR)
#define ATTN_SMEM_U32 (64 * (2 * KSTR + 2 * VSTR))   // 17920 -> 71680 B

__global__ __launch_bounds__(128, 3) void attn_mma()
{
    extern __shared__ __align__(16) uint32_t asm_[];

    const int tid  = threadIdx.x;
    const int warp = tid >> 5;
    const int lane = tid & 31;
    const int g    = lane >> 2;
    const int tg   = lane & 3;

    const int qi = blockIdx.x;
    const int h  = blockIdx.y;
    const int b  = blockIdx.z;
    const int q0 = qi * 64;

    const size_t base = (((size_t)b * H_NUM + h) * S_LEN) * DKH;
    const float* Qg = g_q + base;
    const float* Kg = g_k + base;
    const float* Vg = g_v + base;

    const uint32_t sb = smem_u32(asm_);

    // --- cp.async Q -> Ks buf1 region (group 0), then tile0 (group 1) ---
#pragma unroll
    for (int r = 0; r < 8; r++) {
        const int c   = tid + r * 128;
        const int row = c >> 4;
        const int cbb = (c & 15) * 16;   // byte col within 256B row
        cp16(sb + (KBUF(1) + row * KSTR) * 4 + cbb,
             (const char*)(Qg + (size_t)(q0 + row) * DKH) + cbb);
    }
    CP_COMMIT();
#pragma unroll
    for (int r = 0; r < 8; r++) {
        const int c   = tid + r * 128;
        const int row = c >> 4;
        const int cbb = (c & 15) * 16;
        cp16(sb + (KBUF(0) + row * KSTR) * 4 + cbb,
             (const char*)(Kg + (size_t)row * DKH) + cbb);
        cp16(sb + (VBUF(0) + row * VSTR) * 4 + cbb,
             (const char*)(Vg + (size_t)row * DKH) + cbb);
    }
    CP_COMMIT();

    CP_WAIT1();            // Q done; tile0 may still be in flight
    __syncthreads();

    // extract Q fragments from Ks buf1
    uint32_t qf[8][4];
    const int mrow = 16 * warp + g;
#pragma unroll
    for (int ks = 0; ks < 8; ks++) {
        qf[ks][0] = asm_[KBUF(1) + mrow * KSTR + 8 * ks + tg];
        qf[ks][1] = asm_[KBUF(1) + (mrow + 8) * KSTR + 8 * ks + tg];
        qf[ks][2] = asm_[KBUF(1) + mrow * KSTR + 8 * ks + tg + 4];
        qf[ks][3] = asm_[KBUF(1) + (mrow + 8) * KSTR + 8 * ks + tg + 4];
    }
    __syncthreads();

    // prefetch tile 1 into buf1
    if (qi >= 1) {
#pragma unroll
        for (int r = 0; r < 8; r++) {
            const int c   = tid + r * 128;
            const int row = c >> 4;
            const int cbb = (c & 15) * 16;
            cp16(sb + (KBUF(1) + row * KSTR) * 4 + cbb,
                 (const char*)(Kg + (size_t)(64 + row) * DKH) + cbb);
            cp16(sb + (VBUF(1) + row * VSTR) * 4 + cbb,
                 (const char*)(Vg + (size_t)(64 + row) * DKH) + cbb);
        }
        CP_COMMIT();
    }

    float o[8][4];
#pragma unroll
    for (int nt = 0; nt < 8; nt++)
#pragma unroll
        for (int r = 0; r < 4; r++) o[nt][r] = 0.f;
    float m2a = -1e30f, m2b = -1e30f, la = 0.f, lb = 0.f;

    const float SC = 0.125f * 1.44269504088896341f;  // scale * log2(e)

    for (int t = 0; t <= qi; t++) {
        if (t < qi) { CP_WAIT1(); } else { CP_WAIT0(); }
        __syncthreads();

        const uint32_t* Ks = asm_ + KBUF(t & 1);
        const uint32_t* Vs = asm_ + VBUF(t & 1);

        // S = Q K^T
        float sacc[8][4];
#pragma unroll
        for (int nt = 0; nt < 8; nt++) {
            sacc[nt][0] = 0.f; sacc[nt][1] = 0.f; sacc[nt][2] = 0.f; sacc[nt][3] = 0.f;
            const int n = 8 * nt + g;
#pragma unroll
            for (int ks = 0; ks < 8; ks++) {
                const uint32_t b0 = Ks[n * KSTR + 8 * ks + tg];
                const uint32_t b1 = Ks[n * KSTR + 8 * ks + tg + 4];
                mma_tf32(sacc[nt][0], sacc[nt][1], sacc[nt][2], sacc[nt][3],
                         qf[ks][0], qf[ks][1], qf[ks][2], qf[ks][3], b0, b1);
            }
        }

        // scale (base-2) + causal mask on diagonal tile
#pragma unroll
        for (int nt = 0; nt < 8; nt++) {
#pragma unroll
            for (int r = 0; r < 4; r++) sacc[nt][r] *= SC;
            if (t == qi) {
                const int c0 = 8 * nt + 2 * tg;
                const int ra = 16 * warp + g, rb = ra + 8;
                if (c0 > ra)     sacc[nt][0] = -1e30f;
                if (c0 + 1 > ra) sacc[nt][1] = -1e30f;
                if (c0 > rb)     sacc[nt][2] = -1e30f;
                if (c0 + 1 > rb) sacc[nt][3] = -1e30f;
            }
        }

        // row max -> quad reduce
        float rmaxa = -1e30f, rmaxb = -1e30f;
#pragma unroll
        for (int nt = 0; nt < 8; nt++) {
            rmaxa = fmaxf(rmaxa, fmaxf(sacc[nt][0], sacc[nt][1]));
            rmaxb = fmaxf(rmaxb, fmaxf(sacc[nt][2], sacc[nt][3]));
        }
        rmaxa = fmaxf(rmaxa, __shfl_xor_sync(0xffffffffu, rmaxa, 1));
        rmaxa = fmaxf(rmaxa, __shfl_xor_sync(0xffffffffu, rmaxa, 2));
        rmaxb = fmaxf(rmaxb, __shfl_xor_sync(0xffffffffu, rmaxb, 1));
        rmaxb = fmaxf(rmaxb, __shfl_xor_sync(0xffffffffu, rmaxb, 2));

        const float mna = fmaxf(m2a, rmaxa);
        const float mnb = fmaxf(m2b, rmaxb);
        const float alpa = exp2p(m2a - mna);
        const float alpb = exp2p(m2b - mnb);
        m2a = mna; m2b = mnb;

        // p = 2^(s-m), row sums, convert to tf32 in place
        float rsa = 0.f, rsb = 0.f;
#pragma unroll
        for (int nt = 0; nt < 8; nt++) {
            float p0 = exp2p(sacc[nt][0] - mna);
            float p1 = exp2p(sacc[nt][1] - mna);
            float p2 = exp2p(sacc[nt][2] - mnb);
            float p3 = exp2p(sacc[nt][3] - mnb);
            rsa += p0 + p1; rsb += p2 + p3;
            sacc[nt][0] = __uint_as_float(f2tf32(p0));
            sacc[nt][1] = __uint_as_float(f2tf32(p1));
            sacc[nt][2] = __uint_as_float(f2tf32(p2));
            sacc[nt][3] = __uint_as_float(f2tf32(p3));
        }
        rsa += __shfl_xor_sync(0xffffffffu, rsa, 1);
        rsa += __shfl_xor_sync(0xffffffffu, rsa, 2);
        rsb += __shfl_xor_sync(0xffffffffu, rsb, 1);
        rsb += __shfl_xor_sync(0xffffffffu, rsb, 2);
        la = la * alpa + rsa;
        lb = lb * alpb + rsb;

#pragma unroll
        for (int nt = 0; nt < 8; nt++) {
            o[nt][0] *= alpa; o[nt][1] *= alpa;
            o[nt][2] *= alpb; o[nt][3] *= alpb;
        }

        // O += P V (A-frags gathered via intra-quad shfl; B from row-major Vs)
        const int src0 = (lane & ~3) | (tg >> 1);
        const int src1 = src0 + 2;
#pragma unroll
        for (int ks = 0; ks < 8; ks++) {
            const float x0 = __shfl_sync(0xffffffffu, sacc[ks][0], src0);
            const float x1 = __shfl_sync(0xffffffffu, sacc[ks][1], src0);
            const float x2 = __shfl_sync(0xffffffffu, sacc[ks][2], src0);
            const float x3 = __shfl_sync(0xffffffffu, sacc[ks][3], src0);
            const float y0 = __shfl_sync(0xffffffffu, sacc[ks][0], src1);
            const float y1 = __shfl_sync(0xffffffffu, sacc[ks][1], src1);
            const float y2 = __shfl_sync(0xffffffffu, sacc[ks][2], src1);
            const float y3 = __shfl_sync(0xffffffffu, sacc[ks][3], src1);
            const uint32_t a0 = __float_as_uint((tg & 1) ? x1 : x0);
            const uint32_t a1 = __float_as_uint((tg & 1) ? x3 : x2);
            const uint32_t a2 = __float_as_uint((tg & 1) ? y1 : y0);
            const uint32_t a3 = __float_as_uint((tg & 1) ? y3 : y2);
#pragma unroll
            for (int nt = 0; nt < 8; nt++) {
                const int n = 8 * nt + g;
                const uint32_t b0 = Vs[(8 * ks + tg) * VSTR + n];
                const uint32_t b1 = Vs[(8 * ks + tg + 4) * VSTR + n];
                mma_tf32(o[nt][0], o[nt][1], o[nt][2], o[nt][3],
                         a0, a1, a2, a3, b0, b1);
            }
        }

        __syncthreads();   // all warps done with buf[t&1]

        if (t + 2 <= qi) {
            const int buf = t & 1;
#pragma unroll
            for (int r = 0; r < 8; r++) {
                const int c   = tid + r * 128;
                const int row = c >> 4;
                const int cbb = (c & 15) * 16;
                cp16(sb + (KBUF(buf) + row * KSTR) * 4 + cbb,
                     (const char*)(Kg + (size_t)((t + 2) * 64 + row) * DKH) + cbb);
                cp16(sb + (VBUF(buf) + row * VSTR) * 4 + cbb,
                     (const char*)(Vg + (size_t)((t + 2) * 64 + row) * DKH) + cbb);
            }
            CP_COMMIT();
        }
    }

    // epilogue: normalize, write g_ctx (B,S,E)
    const float inva = 1.0f / la;
    const float invb = 1.0f / lb;
    const int rowa = q0 + 16 * warp + g;
    const int rowb = rowa + 8;
#pragma unroll
    for (int nt = 0; nt < 8; nt++) {
        const int col = h * DKH + 8 * nt + 2 * tg;
        float2 va, vb;
        va.x = o[nt][0] * inva; va.y = o[nt][1] * inva;
        vb.x = o[nt][2] * invb; vb.y = o[nt][3] * invb;
        *(float2*)&g_ctx[((size_t)b * S_LEN + rowa) * E_DIM + col] = va;
        *(float2*)&g_ctx[((size_t)b * S_LEN + rowb) * E_DIM + col] = vb;
    }
}

// ---------------------------------------------------------------------------
extern "C" void kernel_launch(void* const* d_in, const int* in_sizes, int n_in,
                              void* d_out, int out_size)
{
    (void)in_sizes; (void)n_in; (void)out_size;
    const float* x     = (const float*)d_in[0];
    const float* w_in  = (const float*)d_in[1];
    const float* b_in  = (const float*)d_in[2];
    const float* w_out = (const float*)d_in[3];
    const float* b_out = (const float*)d_in[4];
    float* out = (float*)d_out;

    const int gemm_smem = 2 * 128 * STR * (int)sizeof(uint32_t);
    const int attn_smem = ATTN_SMEM_U32 * (int)sizeof(uint32_t);   // 71680 B

    static bool attr_done = false;
    if (!attr_done) {
        cudaFuncSetAttribute(gemm_mma<0>, cudaFuncAttributeMaxDynamicSharedMemorySize, gemm_smem);
        cudaFuncSetAttribute(gemm_mma<1>, cudaFuncAttributeMaxDynamicSharedMemorySize, gemm_smem);
        cudaFuncSetAttribute(attn_mma, cudaFuncAttributeMaxDynamicSharedMemorySize, attn_smem);
        attr_done = true;
    }

    {
        dim3 grid(N_QKV / 128, M_TOT / 128);
        gemm_mma<0><<<grid, 256, gemm_smem>>>(x, w_in, b_in, nullptr);
    }
    {
        dim3 grid(S_LEN / 64, H_NUM, B_SZ);
        attn_mma<<<grid, 128, attn_smem>>>();
    }
    {
        dim3 grid(E_DIM / 128, M_TOT / 128);
        gemm_mma<1><<<grid, 256, gemm_smem>>>(nullptr, w_out, b_out, out);
    }
}

// round 6
// speedup vs baseline: 3.9943x; 1.2189x over previous
#include <cuda_runtime.h>
#include <cstdint>
#include <math.h>

#define E_DIM 1024
#define S_LEN 2048
#define B_SZ  2
#define H_NUM 16
#define DKH   64
#define M_TOT (B_SZ * S_LEN)     // 4096
#define N_QKV (3 * E_DIM)        // 3072

// Scratch (allocation-free: __device__ globals). All hold tf32-rounded bits
// except g_ctx which is rounded by the attention epilogue.
__device__ float g_q[(size_t)B_SZ * H_NUM * S_LEN * DKH];
__device__ float g_k[(size_t)B_SZ * H_NUM * S_LEN * DKH];
__device__ float g_v[(size_t)B_SZ * H_NUM * S_LEN * DKH];
__device__ float g_ctx[(size_t)B_SZ * S_LEN * E_DIM];
__device__ float g_xr[(size_t)M_TOT * E_DIM];     // rounded x
__device__ float g_wir[(size_t)N_QKV * E_DIM];    // rounded w_in
__device__ float g_wor[(size_t)E_DIM * E_DIM];    // rounded w_out

__device__ __forceinline__ uint32_t f2tf32(float x) {
    uint32_t r;
    asm("cvt.rna.tf32.f32 %0, %1;" : "=r"(r) : "f"(x));
    return r;
}

__device__ __forceinline__ uint32_t smem_u32(const void* p) {
    uint32_t a;
    asm("{ .reg .u64 t; cvta.to.shared.u64 t, %1; cvt.u32.u64 %0, t; }"
        : "=r"(a) : "l"(p));
    return a;
}

__device__ __forceinline__ void cp16(uint32_t dst, const void* src) {
    asm volatile("cp.async.cg.shared.global [%0], [%1], 16;"
                 :: "r"(dst), "l"(src) : "memory");
}
#define CP_COMMIT() asm volatile("cp.async.commit_group;" ::: "memory")
#define CP_WAIT0()  asm volatile("cp.async.wait_group 0;" ::: "memory")
#define CP_WAIT1()  asm volatile("cp.async.wait_group 1;" ::: "memory")

__device__ __forceinline__ void mma_tf32(float& c0, float& c1, float& c2, float& c3,
                                         uint32_t a0, uint32_t a1, uint32_t a2, uint32_t a3,
                                         uint32_t b0, uint32_t b1) {
    asm volatile(
        "mma.sync.aligned.m16n8k8.row.col.f32.tf32.tf32.f32 "
        "{%0,%1,%2,%3}, {%4,%5,%6,%7}, {%8,%9}, {%0,%1,%2,%3};"
        : "+f"(c0), "+f"(c1), "+f"(c2), "+f"(c3)
        : "r"(a0), "r"(a1), "r"(a2), "r"(a3), "r"(b0), "r"(b1));
}

// fast 2^y for y <= 0 (clamped). fma/alu pipe only, no MUFU.
__device__ __forceinline__ float exp2p(float y) {
    y = fmaxf(y, -126.0f);
    float n = floorf(y);
    float f = y - n;
    float p = 1.53456767e-4f;
    p = fmaf(p, f, 1.33335581e-3f);
    p = fmaf(p, f, 9.61812910e-3f);
    p = fmaf(p, f, 5.55041087e-2f);
    p = fmaf(p, f, 2.40226507e-1f);
    p = fmaf(p, f, 6.93147181e-1f);
    p = fmaf(p, f, 1.0f);
    const int e = (int)n + 127;
    return p * __int_as_float(e << 23);
}

// ---------------------------------------------------------------------------
// Prepass: round x, w_in, w_out to tf32 bit-patterns in scratch.
// ---------------------------------------------------------------------------
__global__ __launch_bounds__(256) void round_pre(
    const float* __restrict__ x, const float* __restrict__ wi,
    const float* __restrict__ wo)
{
    const int NX  = M_TOT * E_DIM / 4;
    const int NWI = N_QKV * E_DIM / 4;
    const int NWO = E_DIM * E_DIM / 4;
    const int total = NX + NWI + NWO;
    for (int i = blockIdx.x * blockDim.x + threadIdx.x; i < total;
         i += gridDim.x * blockDim.x) {
        const float4* s;
        float4* d;
        int j;
        if (i < NX)            { s = (const float4*)x;  d = (float4*)g_xr;  j = i; }
        else if (i < NX + NWI) { s = (const float4*)wi; d = (float4*)g_wir; j = i - NX; }
        else                   { s = (const float4*)wo; d = (float4*)g_wor; j = i - NX - NWI; }
        float4 v = s[j];
        v.x = __uint_as_float(f2tf32(v.x));
        v.y = __uint_as_float(f2tf32(v.y));
        v.z = __uint_as_float(f2tf32(v.z));
        v.w = __uint_as_float(f2tf32(v.w));
        d[j] = v;
    }
}

// ---------------------------------------------------------------------------
// TF32 mma.sync GEMM, cp.async 3-stage pipeline. Operands pre-rounded.
// C[M,N] = A[M,1024] @ W[N,1024]^T + bias[N]
// 128x128 tile, BK=32, 256 threads (8 warps 2x4), warp tile 64x32.
// MODE 0: A=g_xr, W=g_wir, scatter tf32-rounded q/k/v. MODE 1: A=g_ctx, W=g_wor.
// ---------------------------------------------------------------------------
#define BK 32
#define NKT (E_DIM / BK)
#define STR 36
#define STAGES 3
#define STG_U32 (2 * 128 * STR)           // 9216 u32 = 36864 B per stage
#define GEMM_SMEM (STAGES * STG_U32 * 4)  // 110592 B

template <int MODE>
__global__ __launch_bounds__(256, 2) void gemm_mma(
    const float* __restrict__ bias, float* __restrict__ Cout)
{
    extern __shared__ __align__(16) uint32_t sm[];
    const uint32_t sb = smem_u32(sm);

    const int tid  = threadIdx.x;
    const int warp = tid >> 5;
    const int lane = tid & 31;
    const int g    = lane >> 2;
    const int tg   = lane & 3;
    const int wm   = warp >> 2;
    const int wn   = warp & 3;

    const int m0 = blockIdx.y * 128;
    const int n0 = blockIdx.x * 128;

    const float* A = (MODE == 0 ? (const float*)g_xr  : (const float*)g_ctx);
    const float* W = (MODE == 0 ? (const float*)g_wir : (const float*)g_wor);

    // cp.async geometry: 8 transfers/thread/tile (4 A + 4 B).
    // c = tid + r*256: row = c>>3 (0..127), 16B col = (c&7).
    uint32_t dstA[4], dstB[4];
    const float* srcA[4];
    const float* srcW[4];
#pragma unroll
    for (int r = 0; r < 4; r++) {
        const int c   = tid + r * 256;
        const int row = c >> 3;
        const int cc  = (c & 7) * 4;    // float col
        dstA[r] = sb + (row * STR + cc) * 4;
        dstB[r] = sb + ((128 * STR) + row * STR + cc) * 4;
        srcA[r] = A + (size_t)(m0 + row) * E_DIM + cc;
        srcW[r] = W + (size_t)(n0 + row) * E_DIM + cc;
    }

    // prologue: stage tiles 0..STAGES-2
#pragma unroll
    for (int s = 0; s < STAGES - 1; s++) {
        const uint32_t so = s * STG_U32 * 4;
#pragma unroll
        for (int r = 0; r < 4; r++) {
            cp16(dstA[r] + so, srcA[r] + s * BK);
            cp16(dstB[r] + so, srcW[r] + s * BK);
        }
        CP_COMMIT();
    }

    float acc[4][4][4];
#pragma unroll
    for (int mt = 0; mt < 4; mt++)
#pragma unroll
        for (int nt = 0; nt < 4; nt++)
#pragma unroll
            for (int r = 0; r < 4; r++) acc[mt][nt][r] = 0.f;

    for (int kt = 0; kt < NKT; kt++) {
        if (kt == NKT - 1) { CP_WAIT0(); } else { CP_WAIT1(); }
        __syncthreads();

        // prefetch tile kt+2 into the slot freed at iter kt-1
        const int pf = kt + STAGES - 1;
        if (pf < NKT) {
            const uint32_t so = (pf % STAGES) * STG_U32 * 4;
#pragma unroll
            for (int r = 0; r < 4; r++) {
                cp16(dstA[r] + so, srcA[r] + pf * BK);
                cp16(dstB[r] + so, srcW[r] + pf * BK);
            }
            CP_COMMIT();
        }

        const uint32_t* As = sm + (kt % STAGES) * STG_U32;
        const uint32_t* Bs = As + 128 * STR;

#pragma unroll
        for (int ks = 0; ks < 4; ks++) {
            const int kb = ks * 8;
            uint32_t a[4][4];
#pragma unroll
            for (int mt = 0; mt < 4; mt++) {
                const int m = wm * 64 + mt * 16 + g;
                a[mt][0] = As[m * STR + kb + tg];
                a[mt][1] = As[(m + 8) * STR + kb + tg];
                a[mt][2] = As[m * STR + kb + tg + 4];
                a[mt][3] = As[(m + 8) * STR + kb + tg + 4];
            }
            uint32_t b[4][2];
#pragma unroll
            for (int nt = 0; nt < 4; nt++) {
                const int n = wn * 32 + nt * 8 + g;
                b[nt][0] = Bs[n * STR + kb + tg];
                b[nt][1] = Bs[n * STR + kb + tg + 4];
            }
#pragma unroll
            for (int mt = 0; mt < 4; mt++)
#pragma unroll
                for (int nt = 0; nt < 4; nt++)
                    mma_tf32(acc[mt][nt][0], acc[mt][nt][1],
                             acc[mt][nt][2], acc[mt][nt][3],
                             a[mt][0], a[mt][1], a[mt][2], a[mt][3],
                             b[nt][0], b[nt][1]);
        }
        __syncthreads();
    }

#pragma unroll
    for (int mt = 0; mt < 4; mt++) {
#pragma unroll
        for (int nt = 0; nt < 4; nt++) {
            const int col = n0 + wn * 32 + nt * 8 + 2 * tg;
            const float b0 = bias[col];
            const float b1 = bias[col + 1];
#pragma unroll
            for (int half = 0; half < 2; half++) {
                const int m = m0 + wm * 64 + mt * 16 + g + half * 8;
                float2 v;
                v.x = acc[mt][nt][half * 2 + 0] + b0;
                v.y = acc[mt][nt][half * 2 + 1] + b1;
                if (MODE == 0) {
                    v.x = __uint_as_float(f2tf32(v.x));
                    v.y = __uint_as_float(f2tf32(v.y));
                    const int bb   = m >> 11;
                    const int srow = m & (S_LEN - 1);
                    const int part = col >> 10;
                    const int e    = col & 1023;
                    const int h    = e >> 6;
                    const int d    = e & 63;
                    float* dst = (part == 0) ? g_q : (part == 1) ? g_k : g_v;
                    *(float2*)&dst[((((size_t)bb * H_NUM + h) * S_LEN) + srow) * DKH + d] = v;
                } else {
                    *(float2*)&Cout[(size_t)m * E_DIM + col] = v;
                }
            }
        }
    }
}

// ---------------------------------------------------------------------------
// Tensor-core flash attention, cp.async double-buffered (unchanged from R4
// except epilogue rounds g_ctx to tf32 bits).
// ---------------------------------------------------------------------------
#define KSTR 68
#define VSTR 72
#define KBUF(b) ((b) * 64 * KSTR)
#define VBUF(b) (2 * 64 * KSTR + (b) * 64 * VSTR)
#define ATTN_SMEM_U32 (64 * (2 * KSTR + 2 * VSTR))

__global__ __launch_bounds__(128, 3) void attn_mma()
{
    extern __shared__ __align__(16) uint32_t asm_[];

    const int tid  = threadIdx.x;
    const int warp = tid >> 5;
    const int lane = tid & 31;
    const int g    = lane >> 2;
    const int tg   = lane & 3;

    const int qi = blockIdx.x;
    const int h  = blockIdx.y;
    const int b  = blockIdx.z;
    const int q0 = qi * 64;

    const size_t base = (((size_t)b * H_NUM + h) * S_LEN) * DKH;
    const float* Qg = g_q + base;
    const float* Kg = g_k + base;
    const float* Vg = g_v + base;

    const uint32_t sb = smem_u32(asm_);

#pragma unroll
    for (int r = 0; r < 8; r++) {
        const int c   = tid + r * 128;
        const int row = c >> 4;
        const int cbb = (c & 15) * 16;
        cp16(sb + (KBUF(1) + row * KSTR) * 4 + cbb,
             (const char*)(Qg + (size_t)(q0 + row) * DKH) + cbb);
    }
    CP_COMMIT();
#pragma unroll
    for (int r = 0; r < 8; r++) {
        const int c   = tid + r * 128;
        const int row = c >> 4;
        const int cbb = (c & 15) * 16;
        cp16(sb + (KBUF(0) + row * KSTR) * 4 + cbb,
             (const char*)(Kg + (size_t)row * DKH) + cbb);
        cp16(sb + (VBUF(0) + row * VSTR) * 4 + cbb,
             (const char*)(Vg + (size_t)row * DKH) + cbb);
    }
    CP_COMMIT();

    CP_WAIT1();
    __syncthreads();

    uint32_t qf[8][4];
    const int mrow = 16 * warp + g;
#pragma unroll
    for (int ks = 0; ks < 8; ks++) {
        qf[ks][0] = asm_[KBUF(1) + mrow * KSTR + 8 * ks + tg];
        qf[ks][1] = asm_[KBUF(1) + (mrow + 8) * KSTR + 8 * ks + tg];
        qf[ks][2] = asm_[KBUF(1) + mrow * KSTR + 8 * ks + tg + 4];
        qf[ks][3] = asm_[KBUF(1) + (mrow + 8) * KSTR + 8 * ks + tg + 4];
    }
    __syncthreads();

    if (qi >= 1) {
#pragma unroll
        for (int r = 0; r < 8; r++) {
            const int c   = tid + r * 128;
            const int row = c >> 4;
            const int cbb = (c & 15) * 16;
            cp16(sb + (KBUF(1) + row * KSTR) * 4 + cbb,
                 (const char*)(Kg + (size_t)(64 + row) * DKH) + cbb);
            cp16(sb + (VBUF(1) + row * VSTR) * 4 + cbb,
                 (const char*)(Vg + (size_t)(64 + row) * DKH) + cbb);
        }
        CP_COMMIT();
    }

    float o[8][4];
#pragma unroll
    for (int nt = 0; nt < 8; nt++)
#pragma unroll
        for (int r = 0; r < 4; r++) o[nt][r] = 0.f;
    float m2a = -1e30f, m2b = -1e30f, la = 0.f, lb = 0.f;

    const float SC = 0.125f * 1.44269504088896341f;

    for (int t = 0; t <= qi; t++) {
        if (t < qi) { CP_WAIT1(); } else { CP_WAIT0(); }
        __syncthreads();

        const uint32_t* Ks = asm_ + KBUF(t & 1);
        const uint32_t* Vs = asm_ + VBUF(t & 1);

        float sacc[8][4];
#pragma unroll
        for (int nt = 0; nt < 8; nt++) {
            sacc[nt][0] = 0.f; sacc[nt][1] = 0.f; sacc[nt][2] = 0.f; sacc[nt][3] = 0.f;
            const int n = 8 * nt + g;
#pragma unroll
            for (int ks = 0; ks < 8; ks++) {
                const uint32_t b0 = Ks[n * KSTR + 8 * ks + tg];
                const uint32_t b1 = Ks[n * KSTR + 8 * ks + tg + 4];
                mma_tf32(sacc[nt][0], sacc[nt][1], sacc[nt][2], sacc[nt][3],
                         qf[ks][0], qf[ks][1], qf[ks][2], qf[ks][3], b0, b1);
            }
        }

#pragma unroll
        for (int nt = 0; nt < 8; nt++) {
#pragma unroll
            for (int r = 0; r < 4; r++) sacc[nt][r] *= SC;
            if (t == qi) {
                const int c0 = 8 * nt + 2 * tg;
                const int ra = 16 * warp + g, rb = ra + 8;
                if (c0 > ra)     sacc[nt][0] = -1e30f;
                if (c0 + 1 > ra) sacc[nt][1] = -1e30f;
                if (c0 > rb)     sacc[nt][2] = -1e30f;
                if (c0 + 1 > rb) sacc[nt][3] = -1e30f;
            }
        }

        float rmaxa = -1e30f, rmaxb = -1e30f;
#pragma unroll
        for (int nt = 0; nt < 8; nt++) {
            rmaxa = fmaxf(rmaxa, fmaxf(sacc[nt][0], sacc[nt][1]));
            rmaxb = fmaxf(rmaxb, fmaxf(sacc[nt][2], sacc[nt][3]));
        }
        rmaxa = fmaxf(rmaxa, __shfl_xor_sync(0xffffffffu, rmaxa, 1));
        rmaxa = fmaxf(rmaxa, __shfl_xor_sync(0xffffffffu, rmaxa, 2));
        rmaxb = fmaxf(rmaxb, __shfl_xor_sync(0xffffffffu, rmaxb, 1));
        rmaxb = fmaxf(rmaxb, __shfl_xor_sync(0xffffffffu, rmaxb, 2));

        const float mna = fmaxf(m2a, rmaxa);
        const float mnb = fmaxf(m2b, rmaxb);
        const float alpa = exp2p(m2a - mna);
        const float alpb = exp2p(m2b - mnb);
        m2a = mna; m2b = mnb;

        float rsa = 0.f, rsb = 0.f;
#pragma unroll
        for (int nt = 0; nt < 8; nt++) {
            float p0 = exp2p(sacc[nt][0] - mna);
            float p1 = exp2p(sacc[nt][1] - mna);
            float p2 = exp2p(sacc[nt][2] - mnb);
            float p3 = exp2p(sacc[nt][3] - mnb);
            rsa += p0 + p1; rsb += p2 + p3;
            sacc[nt][0] = __uint_as_float(f2tf32(p0));
            sacc[nt][1] = __uint_as_float(f2tf32(p1));
            sacc[nt][2] = __uint_as_float(f2tf32(p2));
            sacc[nt][3] = __uint_as_float(f2tf32(p3));
        }
        rsa += __shfl_xor_sync(0xffffffffu, rsa, 1);
        rsa += __shfl_xor_sync(0xffffffffu, rsa, 2);
        rsb += __shfl_xor_sync(0xffffffffu, rsb, 1);
        rsb += __shfl_xor_sync(0xffffffffu, rsb, 2);
        la = la * alpa + rsa;
        lb = lb * alpb + rsb;

#pragma unroll
        for (int nt = 0; nt < 8; nt++) {
            o[nt][0] *= alpa; o[nt][1] *= alpa;
            o[nt][2] *= alpb; o[nt][3] *= alpb;
        }

        const int src0 = (lane & ~3) | (tg >> 1);
        const int src1 = src0 + 2;
#pragma unroll
        for (int ks = 0; ks < 8; ks++) {
            const float x0 = __shfl_sync(0xffffffffu, sacc[ks][0], src0);
            const float x1 = __shfl_sync(0xffffffffu, sacc[ks][1], src0);
            const float x2 = __shfl_sync(0xffffffffu, sacc[ks][2], src0);
            const float x3 = __shfl_sync(0xffffffffu, sacc[ks][3], src0);
            const float y0 = __shfl_sync(0xffffffffu, sacc[ks][0], src1);
            const float y1 = __shfl_sync(0xffffffffu, sacc[ks][1], src1);
            const float y2 = __shfl_sync(0xffffffffu, sacc[ks][2], src1);
            const float y3 = __shfl_sync(0xffffffffu, sacc[ks][3], src1);
            const uint32_t a0 = __float_as_uint((tg & 1) ? x1 : x0);
            const uint32_t a1 = __float_as_uint((tg & 1) ? x3 : x2);
            const uint32_t a2 = __float_as_uint((tg & 1) ? y1 : y0);
            const uint32_t a3 = __float_as_uint((tg & 1) ? y3 : y2);
#pragma unroll
            for (int nt = 0; nt < 8; nt++) {
                const int n = 8 * nt + g;
                const uint32_t b0 = Vs[(8 * ks + tg) * VSTR + n];
                const uint32_t b1 = Vs[(8 * ks + tg + 4) * VSTR + n];
                mma_tf32(o[nt][0], o[nt][1], o[nt][2], o[nt][3],
                         a0, a1, a2, a3, b0, b1);
            }
        }

        __syncthreads();

        if (t + 2 <= qi) {
            const int buf = t & 1;
#pragma unroll
            for (int r = 0; r < 8; r++) {
                const int c   = tid + r * 128;
                const int row = c >> 4;
                const int cbb = (c & 15) * 16;
                cp16(sb + (KBUF(buf) + row * KSTR) * 4 + cbb,
                     (const char*)(Kg + (size_t)((t + 2) * 64 + row) * DKH) + cbb);
                cp16(sb + (VBUF(buf) + row * VSTR) * 4 + cbb,
                     (const char*)(Vg + (size_t)((t + 2) * 64 + row) * DKH) + cbb);
            }
            CP_COMMIT();
        }
    }

    // epilogue: normalize, round to tf32 bits, write g_ctx (B,S,E)
    const float inva = 1.0f / la;
    const float invb = 1.0f / lb;
    const int rowa = q0 + 16 * warp + g;
    const int rowb = rowa + 8;
#pragma unroll
    for (int nt = 0; nt < 8; nt++) {
        const int col = h * DKH + 8 * nt + 2 * tg;
        float2 va, vb;
        va.x = __uint_as_float(f2tf32(o[nt][0] * inva));
        va.y = __uint_as_float(f2tf32(o[nt][1] * inva));
        vb.x = __uint_as_float(f2tf32(o[nt][2] * invb));
        vb.y = __uint_as_float(f2tf32(o[nt][3] * invb));
        *(float2*)&g_ctx[((size_t)b * S_LEN + rowa) * E_DIM + col] = va;
        *(float2*)&g_ctx[((size_t)b * S_LEN + rowb) * E_DIM + col] = vb;
    }
}

// ---------------------------------------------------------------------------
extern "C" void kernel_launch(void* const* d_in, const int* in_sizes, int n_in,
                              void* d_out, int out_size)
{
    (void)in_sizes; (void)n_in; (void)out_size;
    const float* x     = (const float*)d_in[0];
    const float* w_in  = (const float*)d_in[1];
    const float* b_in  = (const float*)d_in[2];
    const float* w_out = (const float*)d_in[3];
    const float* b_out = (const float*)d_in[4];
    float* out = (float*)d_out;

    const int attn_smem = ATTN_SMEM_U32 * (int)sizeof(uint32_t);

    static bool attr_done = false;
    if (!attr_done) {
        cudaFuncSetAttribute(gemm_mma<0>, cudaFuncAttributeMaxDynamicSharedMemorySize, GEMM_SMEM);
        cudaFuncSetAttribute(gemm_mma<1>, cudaFuncAttributeMaxDynamicSharedMemorySize, GEMM_SMEM);
        cudaFuncSetAttribute(attn_mma, cudaFuncAttributeMaxDynamicSharedMemorySize, attn_smem);
        attr_done = true;
    }

    // 0) round x / w_in / w_out to tf32 bits
    round_pre<<<2048, 256>>>(x, w_in, w_out);

    // 1) QKV projection
    {
        dim3 grid(N_QKV / 128, M_TOT / 128);
        gemm_mma<0><<<grid, 256, GEMM_SMEM>>>(b_in, nullptr);
    }
    // 2) causal flash attention
    {
        dim3 grid(S_LEN / 64, H_NUM, B_SZ);
        attn_mma<<<grid, 128, attn_smem>>>();
    }
    // 3) output projection
    {
        dim3 grid(E_DIM / 128, M_TOT / 128);
        gemm_mma<1><<<grid, 256, GEMM_SMEM>>>(b_out, out);
    }
}

// round 7
// speedup vs baseline: 4.0000x; 1.0014x over previous
#include <cuda_runtime.h>
#include <cstdint>
#include <math.h>

#define E_DIM 1024
#define S_LEN 2048
#define B_SZ  2
#define H_NUM 16
#define DKH   64
#define M_TOT (B_SZ * S_LEN)     // 4096
#define N_QKV (3 * E_DIM)        // 3072

// Scratch (allocation-free: __device__ globals). All hold tf32-rounded bits.
__device__ float g_q[(size_t)B_SZ * H_NUM * S_LEN * DKH];
__device__ float g_k[(size_t)B_SZ * H_NUM * S_LEN * DKH];
__device__ float g_v[(size_t)B_SZ * H_NUM * S_LEN * DKH];
__device__ float g_ctx[(size_t)B_SZ * S_LEN * E_DIM];
__device__ float g_xr[(size_t)M_TOT * E_DIM];
__device__ float g_wir[(size_t)N_QKV * E_DIM];
__device__ float g_wor[(size_t)E_DIM * E_DIM];

__device__ __forceinline__ uint32_t f2tf32(float x) {
    uint32_t r;
    asm("cvt.rna.tf32.f32 %0, %1;" : "=r"(r) : "f"(x));
    return r;
}

__device__ __forceinline__ uint32_t smem_u32(const void* p) {
    uint32_t a;
    asm("{ .reg .u64 t; cvta.to.shared.u64 t, %1; cvt.u32.u64 %0, t; }"
        : "=r"(a) : "l"(p));
    return a;
}

__device__ __forceinline__ void cp16(uint32_t dst, const void* src) {
    asm volatile("cp.async.cg.shared.global [%0], [%1], 16;"
                 :: "r"(dst), "l"(src) : "memory");
}
#define CP_COMMIT() asm volatile("cp.async.commit_group;" ::: "memory")
#define CP_WAIT0()  asm volatile("cp.async.wait_group 0;" ::: "memory")
#define CP_WAIT1()  asm volatile("cp.async.wait_group 1;" ::: "memory")

__device__ __forceinline__ void mma_tf32(float& c0, float& c1, float& c2, float& c3,
                                         uint32_t a0, uint32_t a1, uint32_t a2, uint32_t a3,
                                         uint32_t b0, uint32_t b1) {
    asm volatile(
        "mma.sync.aligned.m16n8k8.row.col.f32.tf32.tf32.f32 "
        "{%0,%1,%2,%3}, {%4,%5,%6,%7}, {%8,%9}, {%0,%1,%2,%3};"
        : "+f"(c0), "+f"(c1), "+f"(c2), "+f"(c3)
        : "r"(a0), "r"(a1), "r"(a2), "r"(a3), "r"(b0), "r"(b1));
}

// fast 2^y for y <= 0 (clamped). fma/alu pipe only, no MUFU.
__device__ __forceinline__ float exp2p(float y) {
    y = fmaxf(y, -126.0f);
    float n = floorf(y);
    float f = y - n;
    float p = 1.53456767e-4f;
    p = fmaf(p, f, 1.33335581e-3f);
    p = fmaf(p, f, 9.61812910e-3f);
    p = fmaf(p, f, 5.55041087e-2f);
    p = fmaf(p, f, 2.40226507e-1f);
    p = fmaf(p, f, 6.93147181e-1f);
    p = fmaf(p, f, 1.0f);
    const int e = (int)n + 127;
    return p * __int_as_float(e << 23);
}

// ---------------------------------------------------------------------------
// Prepass: round x, w_in, w_out to tf32 bit-patterns in scratch.
// ---------------------------------------------------------------------------
__global__ __launch_bounds__(256) void round_pre(
    const float* __restrict__ x, const float* __restrict__ wi,
    const float* __restrict__ wo)
{
    const int NX  = M_TOT * E_DIM / 4;
    const int NWI = N_QKV * E_DIM / 4;
    const int NWO = E_DIM * E_DIM / 4;
    const int total = NX + NWI + NWO;
    for (int i = blockIdx.x * blockDim.x + threadIdx.x; i < total;
         i += gridDim.x * blockDim.x) {
        const float4* s;
        float4* d;
        int j;
        if (i < NX)            { s = (const float4*)x;  d = (float4*)g_xr;  j = i; }
        else if (i < NX + NWI) { s = (const float4*)wi; d = (float4*)g_wir; j = i - NX; }
        else                   { s = (const float4*)wo; d = (float4*)g_wor; j = i - NX - NWI; }
        float4 v = s[j];
        v.x = __uint_as_float(f2tf32(v.x));
        v.y = __uint_as_float(f2tf32(v.y));
        v.z = __uint_as_float(f2tf32(v.z));
        v.w = __uint_as_float(f2tf32(v.w));
        d[j] = v;
    }
}

// ---------------------------------------------------------------------------
// TF32 mma.sync GEMM, cp.async 3-stage pipeline, 4 warps, warp tile 64x64.
// C[M,N] = A[M,1024] @ W[N,1024]^T + bias[N]; block tile 128x128, BK=32.
// Crossbar bytes/MAC halved vs 8-warp 64x32 (balanced with tensor pipe).
// ---------------------------------------------------------------------------
#define BK 32
#define NKT (E_DIM / BK)
#define STR 36
#define STAGES 3
#define STG_U32 (2 * 128 * STR)           // 9216 u32 = 36864 B per stage
#define GEMM_SMEM (STAGES * STG_U32 * 4)  // 110592 B

template <int MODE>
__global__ __launch_bounds__(128, 2) void gemm_mma(
    const float* __restrict__ bias, float* __restrict__ Cout)
{
    extern __shared__ __align__(16) uint32_t sm[];
    const uint32_t sb = smem_u32(sm);

    const int tid  = threadIdx.x;
    const int warp = tid >> 5;
    const int lane = tid & 31;
    const int g    = lane >> 2;
    const int tg   = lane & 3;
    const int wm   = warp >> 1;        // 0..1 -> rows 64*wm
    const int wn   = warp & 1;         // 0..1 -> cols 64*wn

    const int m0 = blockIdx.y * 128;
    const int n0 = blockIdx.x * 128;

    const float* A = (MODE == 0 ? (const float*)g_xr  : (const float*)g_ctx);
    const float* W = (MODE == 0 ? (const float*)g_wir : (const float*)g_wor);

    // cp.async geometry: 16 transfers/thread/tile (8 A + 8 B), single base.
    // r-th transfer: row = (tid>>3) + 16r, float col = (tid&7)*4.
    const int row0 = tid >> 3;
    const int cc   = (tid & 7) * 4;
    const float* srcA0 = A + (size_t)(m0 + row0) * E_DIM + cc;
    const float* srcW0 = W + (size_t)(n0 + row0) * E_DIM + cc;
    const uint32_t dstA0 = sb + (row0 * STR + cc) * 4;
    const uint32_t dstB0 = dstA0 + 128 * STR * 4;

    // prologue: stage tiles 0..STAGES-2
#pragma unroll
    for (int s = 0; s < STAGES - 1; s++) {
        const uint32_t so = s * STG_U32 * 4;
#pragma unroll
        for (int r = 0; r < 8; r++) {
            cp16(dstA0 + so + r * 16 * STR * 4, srcA0 + (size_t)16 * r * E_DIM + s * BK);
            cp16(dstB0 + so + r * 16 * STR * 4, srcW0 + (size_t)16 * r * E_DIM + s * BK);
        }
        CP_COMMIT();
    }

    float acc[4][8][4];
#pragma unroll
    for (int mt = 0; mt < 4; mt++)
#pragma unroll
        for (int nt = 0; nt < 8; nt++)
#pragma unroll
            for (int r = 0; r < 4; r++) acc[mt][nt][r] = 0.f;

    for (int kt = 0; kt < NKT; kt++) {
        if (kt == NKT - 1) { CP_WAIT0(); } else { CP_WAIT1(); }
        __syncthreads();

        const int pf = kt + STAGES - 1;
        if (pf < NKT) {
            const uint32_t so = (pf % STAGES) * STG_U32 * 4;
#pragma unroll
            for (int r = 0; r < 8; r++) {
                cp16(dstA0 + so + r * 16 * STR * 4, srcA0 + (size_t)16 * r * E_DIM + pf * BK);
                cp16(dstB0 + so + r * 16 * STR * 4, srcW0 + (size_t)16 * r * E_DIM + pf * BK);
            }
            CP_COMMIT();
        }

        const uint32_t* As = sm + (kt % STAGES) * STG_U32;
        const uint32_t* Bs = As + 128 * STR;

#pragma unroll
        for (int ks = 0; ks < 4; ks++) {
            const int kb = ks * 8;
            uint32_t a[4][4];
#pragma unroll
            for (int mt = 0; mt < 4; mt++) {
                const int m = wm * 64 + mt * 16 + g;
                a[mt][0] = As[m * STR + kb + tg];
                a[mt][1] = As[(m + 8) * STR + kb + tg];
                a[mt][2] = As[m * STR + kb + tg + 4];
                a[mt][3] = As[(m + 8) * STR + kb + tg + 4];
            }
            uint32_t b[8][2];
#pragma unroll
            for (int nt = 0; nt < 8; nt++) {
                const int n = wn * 64 + nt * 8 + g;
                b[nt][0] = Bs[n * STR + kb + tg];
                b[nt][1] = Bs[n * STR + kb + tg + 4];
            }
#pragma unroll
            for (int mt = 0; mt < 4; mt++)
#pragma unroll
                for (int nt = 0; nt < 8; nt++)
                    mma_tf32(acc[mt][nt][0], acc[mt][nt][1],
                             acc[mt][nt][2], acc[mt][nt][3],
                             a[mt][0], a[mt][1], a[mt][2], a[mt][3],
                             b[nt][0], b[nt][1]);
        }
        __syncthreads();
    }

#pragma unroll
    for (int mt = 0; mt < 4; mt++) {
#pragma unroll
        for (int nt = 0; nt < 8; nt++) {
            const int col = n0 + wn * 64 + nt * 8 + 2 * tg;
            const float b0 = bias[col];
            const float b1 = bias[col + 1];
#pragma unroll
            for (int half = 0; half < 2; half++) {
                const int m = m0 + wm * 64 + mt * 16 + g + half * 8;
                float2 v;
                v.x = acc[mt][nt][half * 2 + 0] + b0;
                v.y = acc[mt][nt][half * 2 + 1] + b1;
                if (MODE == 0) {
                    v.x = __uint_as_float(f2tf32(v.x));
                    v.y = __uint_as_float(f2tf32(v.y));
                    const int bb   = m >> 11;
                    const int srow = m & (S_LEN - 1);
                    const int part = col >> 10;
                    const int e    = col & 1023;
                    const int h    = e >> 6;
                    const int d    = e & 63;
                    float* dst = (part == 0) ? g_q : (part == 1) ? g_k : g_v;
                    *(float2*)&dst[((((size_t)bb * H_NUM + h) * S_LEN) + srow) * DKH + d] = v;
                } else {
                    *(float2*)&Cout[(size_t)m * E_DIM + col] = v;
                }
            }
        }
    }
}

// ---------------------------------------------------------------------------
// Tensor-core flash attention, cp.async double-buffered (unchanged from R5).
// ---------------------------------------------------------------------------
#define KSTR 68
#define VSTR 72
#define KBUF(b) ((b) * 64 * KSTR)
#define VBUF(b) (2 * 64 * KSTR + (b) * 64 * VSTR)
#define ATTN_SMEM_U32 (64 * (2 * KSTR + 2 * VSTR))

__global__ __launch_bounds__(128, 3) void attn_mma()
{
    extern __shared__ __align__(16) uint32_t asm_[];

    const int tid  = threadIdx.x;
    const int warp = tid >> 5;
    const int lane = tid & 31;
    const int g    = lane >> 2;
    const int tg   = lane & 3;

    const int qi = blockIdx.x;
    const int h  = blockIdx.y;
    const int b  = blockIdx.z;
    const int q0 = qi * 64;

    const size_t base = (((size_t)b * H_NUM + h) * S_LEN) * DKH;
    const float* Qg = g_q + base;
    const float* Kg = g_k + base;
    const float* Vg = g_v + base;

    const uint32_t sb = smem_u32(asm_);

#pragma unroll
    for (int r = 0; r < 8; r++) {
        const int c   = tid + r * 128;
        const int row = c >> 4;
        const int cbb = (c & 15) * 16;
        cp16(sb + (KBUF(1) + row * KSTR) * 4 + cbb,
             (const char*)(Qg + (size_t)(q0 + row) * DKH) + cbb);
    }
    CP_COMMIT();
#pragma unroll
    for (int r = 0; r < 8; r++) {
        const int c   = tid + r * 128;
        const int row = c >> 4;
        const int cbb = (c & 15) * 16;
        cp16(sb + (KBUF(0) + row * KSTR) * 4 + cbb,
             (const char*)(Kg + (size_t)row * DKH) + cbb);
        cp16(sb + (VBUF(0) + row * VSTR) * 4 + cbb,
             (const char*)(Vg + (size_t)row * DKH) + cbb);
    }
    CP_COMMIT();

    CP_WAIT1();
    __syncthreads();

    uint32_t qf[8][4];
    const int mrow = 16 * warp + g;
#pragma unroll
    for (int ks = 0; ks < 8; ks++) {
        qf[ks][0] = asm_[KBUF(1) + mrow * KSTR + 8 * ks + tg];
        qf[ks][1] = asm_[KBUF(1) + (mrow + 8) * KSTR + 8 * ks + tg];
        qf[ks][2] = asm_[KBUF(1) + mrow * KSTR + 8 * ks + tg + 4];
        qf[ks][3] = asm_[KBUF(1) + (mrow + 8) * KSTR + 8 * ks + tg + 4];
    }
    __syncthreads();

    if (qi >= 1) {
#pragma unroll
        for (int r = 0; r < 8; r++) {
            const int c   = tid + r * 128;
            const int row = c >> 4;
            const int cbb = (c & 15) * 16;
            cp16(sb + (KBUF(1) + row * KSTR) * 4 + cbb,
                 (const char*)(Kg + (size_t)(64 + row) * DKH) + cbb);
            cp16(sb + (VBUF(1) + row * VSTR) * 4 + cbb,
                 (const char*)(Vg + (size_t)(64 + row) * DKH) + cbb);
        }
        CP_COMMIT();
    }

    float o[8][4];
#pragma unroll
    for (int nt = 0; nt < 8; nt++)
#pragma unroll
        for (int r = 0; r < 4; r++) o[nt][r] = 0.f;
    float m2a = -1e30f, m2b = -1e30f, la = 0.f, lb = 0.f;

    const float SC = 0.125f * 1.44269504088896341f;

    for (int t = 0; t <= qi; t++) {
        if (t < qi) { CP_WAIT1(); } else { CP_WAIT0(); }
        __syncthreads();

        const uint32_t* Ks = asm_ + KBUF(t & 1);
        const uint32_t* Vs = asm_ + VBUF(t & 1);

        float sacc[8][4];
#pragma unroll
        for (int nt = 0; nt < 8; nt++) {
            sacc[nt][0] = 0.f; sacc[nt][1] = 0.f; sacc[nt][2] = 0.f; sacc[nt][3] = 0.f;
            const int n = 8 * nt + g;
#pragma unroll
            for (int ks = 0; ks < 8; ks++) {
                const uint32_t b0 = Ks[n * KSTR + 8 * ks + tg];
                const uint32_t b1 = Ks[n * KSTR + 8 * ks + tg + 4];
                mma_tf32(sacc[nt][0], sacc[nt][1], sacc[nt][2], sacc[nt][3],
                         qf[ks][0], qf[ks][1], qf[ks][2], qf[ks][3], b0, b1);
            }
        }

#pragma unroll
        for (int nt = 0; nt < 8; nt++) {
#pragma unroll
            for (int r = 0; r < 4; r++) sacc[nt][r] *= SC;
            if (t == qi) {
                const int c0 = 8 * nt + 2 * tg;
                const int ra = 16 * warp + g, rb = ra + 8;
                if (c0 > ra)     sacc[nt][0] = -1e30f;
                if (c0 + 1 > ra) sacc[nt][1] = -1e30f;
                if (c0 > rb)     sacc[nt][2] = -1e30f;
                if (c0 + 1 > rb) sacc[nt][3] = -1e30f;
            }
        }

        float rmaxa = -1e30f, rmaxb = -1e30f;
#pragma unroll
        for (int nt = 0; nt < 8; nt++) {
            rmaxa = fmaxf(rmaxa, fmaxf(sacc[nt][0], sacc[nt][1]));
            rmaxb = fmaxf(rmaxb, fmaxf(sacc[nt][2], sacc[nt][3]));
        }
        rmaxa = fmaxf(rmaxa, __shfl_xor_sync(0xffffffffu, rmaxa, 1));
        rmaxa = fmaxf(rmaxa, __shfl_xor_sync(0xffffffffu, rmaxa, 2));
        rmaxb = fmaxf(rmaxb, __shfl_xor_sync(0xffffffffu, rmaxb, 1));
        rmaxb = fmaxf(rmaxb, __shfl_xor_sync(0xffffffffu, rmaxb, 2));

        const float mna = fmaxf(m2a, rmaxa);
        const float mnb = fmaxf(m2b, rmaxb);
        const float alpa = exp2p(m2a - mna);
        const float alpb = exp2p(m2b - mnb);
        m2a = mna; m2b = mnb;

        float rsa = 0.f, rsb = 0.f;
#pragma unroll
        for (int nt = 0; nt < 8; nt++) {
            float p0 = exp2p(sacc[nt][0] - mna);
            float p1 = exp2p(sacc[nt][1] - mna);
            float p2 = exp2p(sacc[nt][2] - mnb);
            float p3 = exp2p(sacc[nt][3] - mnb);
            rsa += p0 + p1; rsb += p2 + p3;
            sacc[nt][0] = __uint_as_float(f2tf32(p0));
            sacc[nt][1] = __uint_as_float(f2tf32(p1));
            sacc[nt][2] = __uint_as_float(f2tf32(p2));
            sacc[nt][3] = __uint_as_float(f2tf32(p3));
        }
        rsa += __shfl_xor_sync(0xffffffffu, rsa, 1);
        rsa += __shfl_xor_sync(0xffffffffu, rsa, 2);
        rsb += __shfl_xor_sync(0xffffffffu, rsb, 1);
        rsb += __shfl_xor_sync(0xffffffffu, rsb, 2);
        la = la * alpa + rsa;
        lb = lb * alpb + rsb;

#pragma unroll
        for (int nt = 0; nt < 8; nt++) {
            o[nt][0] *= alpa; o[nt][1] *= alpa;
            o[nt][2] *= alpb; o[nt][3] *= alpb;
        }

        const int src0 = (lane & ~3) | (tg >> 1);
        const int src1 = src0 + 2;
#pragma unroll
        for (int ks = 0; ks < 8; ks++) {
            const float x0 = __shfl_sync(0xffffffffu, sacc[ks][0], src0);
            const float x1 = __shfl_sync(0xffffffffu, sacc[ks][1], src0);
            const float x2 = __shfl_sync(0xffffffffu, sacc[ks][2], src0);
            const float x3 = __shfl_sync(0xffffffffu, sacc[ks][3], src0);
            const float y0 = __shfl_sync(0xffffffffu, sacc[ks][0], src1);
            const float y1 = __shfl_sync(0xffffffffu, sacc[ks][1], src1);
            const float y2 = __shfl_sync(0xffffffffu, sacc[ks][2], src1);
            const float y3 = __shfl_sync(0xffffffffu, sacc[ks][3], src1);
            const uint32_t a0 = __float_as_uint((tg & 1) ? x1 : x0);
            const uint32_t a1 = __float_as_uint((tg & 1) ? x3 : x2);
            const uint32_t a2 = __float_as_uint((tg & 1) ? y1 : y0);
            const uint32_t a3 = __float_as_uint((tg & 1) ? y3 : y2);
#pragma unroll
            for (int nt = 0; nt < 8; nt++) {
                const int n = 8 * nt + g;
                const uint32_t b0 = Vs[(8 * ks + tg) * VSTR + n];
                const uint32_t b1 = Vs[(8 * ks + tg + 4) * VSTR + n];
                mma_tf32(o[nt][0], o[nt][1], o[nt][2], o[nt][3],
                         a0, a1, a2, a3, b0, b1);
            }
        }

        __syncthreads();

        if (t + 2 <= qi) {
            const int buf = t & 1;
#pragma unroll
            for (int r = 0; r < 8; r++) {
                const int c   = tid + r * 128;
                const int row = c >> 4;
                const int cbb = (c & 15) * 16;
                cp16(sb + (KBUF(buf) + row * KSTR) * 4 + cbb,
                     (const char*)(Kg + (size_t)((t + 2) * 64 + row) * DKH) + cbb);
                cp16(sb + (VBUF(buf) + row * VSTR) * 4 + cbb,
                     (const char*)(Vg + (size_t)((t + 2) * 64 + row) * DKH) + cbb);
            }
            CP_COMMIT();
        }
    }

    const float inva = 1.0f / la;
    const float invb = 1.0f / lb;
    const int rowa = q0 + 16 * warp + g;
    const int rowb = rowa + 8;
#pragma unroll
    for (int nt = 0; nt < 8; nt++) {
        const int col = h * DKH + 8 * nt + 2 * tg;
        float2 va, vb;
        va.x = __uint_as_float(f2tf32(o[nt][0] * inva));
        va.y = __uint_as_float(f2tf32(o[nt][1] * inva));
        vb.x = __uint_as_float(f2tf32(o[nt][2] * invb));
        vb.y = __uint_as_float(f2tf32(o[nt][3] * invb));
        *(float2*)&g_ctx[((size_t)b * S_LEN + rowa) * E_DIM + col] = va;
        *(float2*)&g_ctx[((size_t)b * S_LEN + rowb) * E_DIM + col] = vb;
    }
}

// ---------------------------------------------------------------------------
extern "C" void kernel_launch(void* const* d_in, const int* in_sizes, int n_in,
                              void* d_out, int out_size)
{
    (void)in_sizes; (void)n_in; (void)out_size;
    const float* x     = (const float*)d_in[0];
    const float* w_in  = (const float*)d_in[1];
    const float* b_in  = (const float*)d_in[2];
    const float* w_out = (const float*)d_in[3];
    const float* b_out = (const float*)d_in[4];
    float* out = (float*)d_out;

    const int attn_smem = ATTN_SMEM_U32 * (int)sizeof(uint32_t);

    static bool attr_done = false;
    if (!attr_done) {
        cudaFuncSetAttribute(gemm_mma<0>, cudaFuncAttributeMaxDynamicSharedMemorySize, GEMM_SMEM);
        cudaFuncSetAttribute(gemm_mma<1>, cudaFuncAttributeMaxDynamicSharedMemorySize, GEMM_SMEM);
        cudaFuncSetAttribute(attn_mma, cudaFuncAttributeMaxDynamicSharedMemorySize, attn_smem);
        attr_done = true;
    }

    // 0) round x / w_in / w_out to tf32 bits
    round_pre<<<2048, 256>>>(x, w_in, w_out);

    // 1) QKV projection
    {
        dim3 grid(N_QKV / 128, M_TOT / 128);
        gemm_mma<0><<<grid, 128, GEMM_SMEM>>>(b_in, nullptr);
    }
    // 2) causal flash attention
    {
        dim3 grid(S_LEN / 64, H_NUM, B_SZ);
        attn_mma<<<grid, 128, attn_smem>>>();
    }
    // 3) output projection
    {
        dim3 grid(E_DIM / 128, M_TOT / 128);
        gemm_mma<1><<<grid, 128, GEMM_SMEM>>>(b_out, out);
    }
}